// round 1
// baseline (speedup 1.0000x reference)
#include <cuda_runtime.h>

#define N_NODES 10000
#define N_EDGES 160000
#define C_IN    1024
#define C_OUT   512
#define C_H     1024
#define NOUT    ((size_t)N_NODES * C_OUT)

// ---------------- scratch (static device globals; no allocations) ----------
__device__ float g_xnorm[(size_t)N_NODES * C_IN];   // 40 MB
__device__ float g_sx   [(size_t)N_NODES * C_IN];   // 40 MB  (S * xnorm)
__device__ float g_h    [(size_t)N_NODES * C_H];    // 40 MB
__device__ float g_sh   [(size_t)N_NODES * C_H];    // 40 MB  (S * h)
__device__ float g_W2   [C_H * 1024];               // [Wm | Ws] packed, 4 MB
__device__ float g_b2   [1024];
__device__ float g_colsum [C_IN];
__device__ float g_colsum2[C_IN];
__device__ float g_A[C_IN];
__device__ float g_B[C_IN];
__device__ float g_dis[N_NODES];                    // deg^{-1/2}
__device__ int   g_deg[N_NODES];
__device__ int   g_ei32[2 * N_EDGES];               // normalized int32 edges
__device__ int   g_flag32;                          // 1 if input edges are int32

// ---------------- setup kernels --------------------------------------------
__global__ void zero_k() {
    int i = blockIdx.x * blockDim.x + threadIdx.x;
    if (i < C_IN)    { g_colsum[i] = 0.f; g_colsum2[i] = 0.f; }
    if (i < N_NODES) { g_deg[i] = 0; }
    if (i == 0)      { g_flag32 = 0; }
}

// Detect edge dtype: reading the first E entries as int64 stays in-bounds for
// both widths. True int64 data is all in [0, N); int32 pairs reinterpreted as
// int64 are almost all >= 2^32 -> flag fires.
__global__ void detect_k(const long long* __restrict__ ei) {
    int i = blockIdx.x * blockDim.x + threadIdx.x;
    if (i < N_EDGES) {
        long long v = ei[i];
        if (v < 0 || v >= N_NODES) atomicOr(&g_flag32, 1);
    }
}

__global__ void convert_k(const void* __restrict__ ei) {
    int i = blockIdx.x * blockDim.x + threadIdx.x;
    if (i >= 2 * N_EDGES) return;
    g_ei32[i] = g_flag32 ? ((const int*)ei)[i]
                         : (int)((const long long*)ei)[i];
}

__global__ void pack_k(const float* __restrict__ Wm, const float* __restrict__ bm,
                       const float* __restrict__ Ws, const float* __restrict__ bs) {
    int i = blockIdx.x * blockDim.x + threadIdx.x;
    if (i < 1024 * 1024) {
        int k = i >> 10, j = i & 1023;
        g_W2[i] = (j < C_OUT) ? Wm[k * C_OUT + j] : Ws[k * C_OUT + (j - C_OUT)];
    }
    if (i < 1024) g_b2[i] = (i < C_OUT) ? bm[i] : bs[i - C_OUT];
}

// Column sums for GraphNorm stats. grid (4, 40): 1024 cols x 40 row-chunks.
__global__ void colstats_k(const float* __restrict__ x) {
    int col = blockIdx.x * 256 + threadIdx.x;
    int r0  = blockIdx.y * 250;
    float s = 0.f, s2 = 0.f;
    for (int r = r0; r < r0 + 250; r++) {
        float v = x[(size_t)r * C_IN + col];
        s += v; s2 += v * v;
    }
    atomicAdd(&g_colsum[col], s);
    atomicAdd(&g_colsum2[col], s2);
}

__global__ void stats_k(const float* __restrict__ w, const float* __restrict__ b,
                        const float* __restrict__ ms) {
    int j = blockIdx.x * blockDim.x + threadIdx.x;
    if (j >= C_IN) return;
    float m   = g_colsum[j]  * (1.f / N_NODES);
    float ex2 = g_colsum2[j] * (1.f / N_NODES);
    float s   = ms[j];
    // var of (x - s*m): E[x^2] - 2 s m E[x] + s^2 m^2
    float var = ex2 - 2.f * s * m * m + s * s * m * m;
    float Aj  = rsqrtf(var + 1e-5f) * w[j];
    g_A[j] = Aj;
    g_B[j] = b[j] - s * m * Aj;
}

__global__ void deg_k() {
    int e = blockIdx.x * blockDim.x + threadIdx.x;
    if (e < N_EDGES) atomicAdd(&g_deg[g_ei32[N_EDGES + e]], 1);
}

__global__ void dis_k() {
    int i = blockIdx.x * blockDim.x + threadIdx.x;
    if (i < N_NODES) g_dis[i] = rsqrtf((float)g_deg[i] + 1.0f);  // +1 self loop
}

// GraphNorm elementwise + seed g_sx with the self-loop term dis^2 * xnorm.
__global__ void xnorm_k(const float* __restrict__ x) {
    int i = blockIdx.x * blockDim.x + threadIdx.x;   // over N*IN/4
    int row = i >> 8;
    if (row >= N_NODES) return;
    int c4 = i & 255;
    float4 xv = ((const float4*)x)[i];
    float4 Av = ((const float4*)g_A)[c4];
    float4 Bv = ((const float4*)g_B)[c4];
    float4 o;
    o.x = fmaf(xv.x, Av.x, Bv.x);
    o.y = fmaf(xv.y, Av.y, Bv.y);
    o.z = fmaf(xv.z, Av.z, Bv.z);
    o.w = fmaf(xv.w, Av.w, Bv.w);
    ((float4*)g_xnorm)[i] = o;
    float dd = g_dis[row]; dd *= dd;
    float4 sv = make_float4(dd * o.x, dd * o.y, dd * o.z, dd * o.w);
    ((float4*)g_sx)[i] = sv;
}

// Edge-parallel SpMM accumulate: out[dst] += dis[src]*dis[dst] * feat[src].
// One block handles 8 edges; each thread owns one float4 (256*4 = 1024 feats).
template<int PH>
__global__ __launch_bounds__(256) void spmm_k() {
    const float* __restrict__ feat = (PH == 0) ? g_xnorm : g_h;
    float* __restrict__ out        = (PH == 0) ? g_sx    : g_sh;
    int t = threadIdx.x;
    #pragma unroll 1
    for (int it = 0; it < 8; it++) {
        int e = blockIdx.x * 8 + it;
        int s = g_ei32[e];
        int d = g_ei32[N_EDGES + e];
        float w = g_dis[s] * g_dis[d];
        float4 v = ((const float4*)(feat + (size_t)s * 1024))[t];
        float* dst = out + (size_t)d * 1024 + t * 4;
        asm volatile("red.global.add.v4.f32 [%0], {%1,%2,%3,%4};"
                     :: "l"(dst), "f"(w * v.x), "f"(w * v.y),
                        "f"(w * v.z), "f"(w * v.w) : "memory");
    }
}

// ---------------- fp32 SIMT GEMM, 128x128 tile, BK=16, double-buffered -----
// MODE 0: h = leaky(g_sx @ W1 + b1)        -> g_h, and g_sh = dis^2 * h
// MODE 1: o = g_sh @ g_W2 + g_b2           -> d_out split (z, mu, logstd)
#define BM 128
#define BN 128
#define BK 16

template<int MODE>
__global__ __launch_bounds__(256) void gemm_k(const float* __restrict__ Bext,
                                              const float* __restrict__ biasext,
                                              float* __restrict__ outext) {
    const float* __restrict__ Ap   = (MODE == 0) ? g_sx : g_sh;
    const float* __restrict__ Bp   = (MODE == 0) ? Bext : g_W2;
    const float* __restrict__ bias = (MODE == 0) ? biasext : g_b2;
    const int M = N_NODES, K = 1024, NC = 1024;

    __shared__ float As[2][BK * BM];
    __shared__ float Bs[2][BK * BN];

    int tid  = threadIdx.x;
    int col0 = blockIdx.x * BN;
    int row0 = blockIdx.y * BM;
    int tx = tid & 15, ty = tid >> 4;

    int ar0 = tid >> 2,  ak = (tid & 3) << 2;   // A: 128 rows x 4 float4/row
    int ar1 = ar0 + 64;
    int br0 = tid >> 5,  bq = (tid & 31) << 2;  // B: 16 rows x 32 float4/row
    int br1 = br0 + 8;

    const float4 z4 = make_float4(0.f, 0.f, 0.f, 0.f);
    float4 la0, la1, lb0, lb1;

    // prologue: load tile 0
    la0 = (row0 + ar0 < M) ? *(const float4*)(Ap + (size_t)(row0 + ar0) * K + ak) : z4;
    la1 = (row0 + ar1 < M) ? *(const float4*)(Ap + (size_t)(row0 + ar1) * K + ak) : z4;
    lb0 = *(const float4*)(Bp + (size_t)br0 * NC + col0 + bq);
    lb1 = *(const float4*)(Bp + (size_t)br1 * NC + col0 + bq);
    As[0][(ak + 0) * BM + ar0] = la0.x; As[0][(ak + 1) * BM + ar0] = la0.y;
    As[0][(ak + 2) * BM + ar0] = la0.z; As[0][(ak + 3) * BM + ar0] = la0.w;
    As[0][(ak + 0) * BM + ar1] = la1.x; As[0][(ak + 1) * BM + ar1] = la1.y;
    As[0][(ak + 2) * BM + ar1] = la1.z; As[0][(ak + 3) * BM + ar1] = la1.w;
    *(float4*)&Bs[0][br0 * BN + bq] = lb0;
    *(float4*)&Bs[0][br1 * BN + bq] = lb1;
    __syncthreads();

    float acc[8][8];
    #pragma unroll
    for (int i = 0; i < 8; i++)
        #pragma unroll
        for (int j = 0; j < 8; j++) acc[i][j] = 0.f;

    const int KT = K / BK;
    for (int kt = 0; kt < KT; kt++) {
        int cur = kt & 1;
        if (kt + 1 < KT) {
            int k0 = (kt + 1) * BK;
            la0 = (row0 + ar0 < M) ? *(const float4*)(Ap + (size_t)(row0 + ar0) * K + k0 + ak) : z4;
            la1 = (row0 + ar1 < M) ? *(const float4*)(Ap + (size_t)(row0 + ar1) * K + k0 + ak) : z4;
            lb0 = *(const float4*)(Bp + (size_t)(k0 + br0) * NC + col0 + bq);
            lb1 = *(const float4*)(Bp + (size_t)(k0 + br1) * NC + col0 + bq);
        }
        #pragma unroll
        for (int k = 0; k < BK; k++) {
            float ra[8], rb[8];
            *(float4*)&ra[0] = *(const float4*)&As[cur][k * BM + ty * 8];
            *(float4*)&ra[4] = *(const float4*)&As[cur][k * BM + ty * 8 + 4];
            *(float4*)&rb[0] = *(const float4*)&Bs[cur][k * BN + tx * 8];
            *(float4*)&rb[4] = *(const float4*)&Bs[cur][k * BN + tx * 8 + 4];
            #pragma unroll
            for (int i = 0; i < 8; i++)
                #pragma unroll
                for (int j = 0; j < 8; j++)
                    acc[i][j] = fmaf(ra[i], rb[j], acc[i][j]);
        }
        if (kt + 1 < KT) {
            int nb = cur ^ 1;
            As[nb][(ak + 0) * BM + ar0] = la0.x; As[nb][(ak + 1) * BM + ar0] = la0.y;
            As[nb][(ak + 2) * BM + ar0] = la0.z; As[nb][(ak + 3) * BM + ar0] = la0.w;
            As[nb][(ak + 0) * BM + ar1] = la1.x; As[nb][(ak + 1) * BM + ar1] = la1.y;
            As[nb][(ak + 2) * BM + ar1] = la1.z; As[nb][(ak + 3) * BM + ar1] = la1.w;
            *(float4*)&Bs[nb][br0 * BN + bq] = lb0;
            *(float4*)&Bs[nb][br1 * BN + bq] = lb1;
        }
        __syncthreads();
    }

    #pragma unroll
    for (int i = 0; i < 8; i++) {
        int r = row0 + ty * 8 + i;
        if (r >= M) continue;
        float dd = 0.f;
        if (MODE == 0) { dd = g_dis[r]; dd *= dd; }
        #pragma unroll
        for (int j = 0; j < 8; j++) {
            int c = col0 + tx * 8 + j;
            float v = acc[i][j] + bias[c];
            if (MODE == 0) {
                v = (v > 0.f) ? v : 0.1f * v;                 // leaky relu
                g_h [(size_t)r * 1024 + c] = v;
                g_sh[(size_t)r * 1024 + c] = dd * v;          // self-loop seed
            } else {
                if (c < C_OUT) {
                    outext[(size_t)r * C_OUT + c]        = v; // z = mu
                    outext[NOUT + (size_t)r * C_OUT + c] = v; // mu
                } else {
                    outext[2 * NOUT + (size_t)r * C_OUT + (c - C_OUT)] = v; // logstd
                }
            }
        }
    }
}

// ---------------- launcher --------------------------------------------------
extern "C" void kernel_launch(void* const* d_in, const int* in_sizes, int n_in,
                              void* d_out, int out_size) {
    const float* x   = (const float*)d_in[0];
    const void*  ei  = d_in[1];
    const float* W1  = (const float*)d_in[2];
    const float* b1  = (const float*)d_in[3];
    const float* Wm  = (const float*)d_in[4];
    const float* bm  = (const float*)d_in[5];
    const float* Ws  = (const float*)d_in[6];
    const float* bs  = (const float*)d_in[7];
    const float* gw  = (const float*)d_in[8];
    const float* gb  = (const float*)d_in[9];
    const float* gms = (const float*)d_in[10];
    float* out = (float*)d_out;

    zero_k   <<<40, 256>>>();
    detect_k <<<(N_EDGES + 255) / 256, 256>>>((const long long*)ei);
    convert_k<<<(2 * N_EDGES + 255) / 256, 256>>>(ei);
    pack_k   <<<4096, 256>>>(Wm, bm, Ws, bs);
    colstats_k<<<dim3(4, 40), 256>>>(x);
    stats_k  <<<4, 256>>>(gw, gb, gms);
    deg_k    <<<(N_EDGES + 255) / 256, 256>>>();
    dis_k    <<<(N_NODES + 255) / 256, 256>>>();
    xnorm_k  <<<(N_NODES * C_IN / 4 + 255) / 256, 256>>>(x);
    spmm_k<0><<<N_EDGES / 8, 256>>>();
    gemm_k<0><<<dim3(1024 / BN, (N_NODES + BM - 1) / BM), 256>>>(W1, b1, nullptr);
    spmm_k<1><<<N_EDGES / 8, 256>>>();
    gemm_k<1><<<dim3(1024 / BN, (N_NODES + BM - 1) / BM), 256>>>(nullptr, nullptr, out);
}

// round 5
// speedup vs baseline: 1.6415x; 1.6415x over previous
#include <cuda_runtime.h>
#include <cuda_bf16.h>
#include <cstdint>

#define N_NODES 10000
#define N_EDGES 160000
#define C_IN    1024
#define C_OUT   512
#define KP      3072                       // 3-way split K'
#define NOUT    ((size_t)N_NODES * C_OUT)

// ---------------- scratch (static device globals; no allocations) ----------
__device__ float g_xnorm[(size_t)N_NODES * C_IN];
__device__ float g_sx   [(size_t)N_NODES * C_IN];
__device__ float g_h    [(size_t)N_NODES * 1024];
__device__ float g_sh   [(size_t)N_NODES * 1024];
__device__ float g_colsum [C_IN];
__device__ float g_colsum2[C_IN];
__device__ float g_A[C_IN];
__device__ float g_B[C_IN];
__device__ float g_dis[N_NODES];
__device__ int   g_deg[N_NODES];
__device__ int   g_ei32[2 * N_EDGES];
__device__ int   g_flag32;
__device__ int   g_mma_ok;
// bf16 B operand [n][k'] with K-segments [hi, hi, lo]  (6.3 MB)
__device__ __nv_bfloat16 g_bh[(size_t)1024 * KP];

// ---------------- mma helper -------------------------------------------------
__device__ __forceinline__ void mma16816(float* d, const uint32_t* a, const uint32_t* b) {
    asm volatile(
        "mma.sync.aligned.m16n8k16.row.col.f32.bf16.bf16.f32 "
        "{%0,%1,%2,%3}, {%4,%5,%6,%7}, {%8,%9}, {%0,%1,%2,%3};"
        : "+f"(d[0]), "+f"(d[1]), "+f"(d[2]), "+f"(d[3])
        : "r"(a[0]), "r"(a[1]), "r"(a[2]), "r"(a[3]), "r"(b[0]), "r"(b[1]));
}

// Canary: one mma with known data. A cols alternate 1,2 (k even/odd), B all 1.
// Every D element = 8*1 + 8*2 = 24.
__global__ void canary_k() {
    float d[4] = {0.f, 0.f, 0.f, 0.f};
    __nv_bfloat162 av2 = __floats2bfloat162_rn(1.f, 2.f);
    __nv_bfloat162 bv2 = __floats2bfloat162_rn(1.f, 1.f);
    uint32_t av = *(uint32_t*)&av2, bv = *(uint32_t*)&bv2;
    uint32_t a[4] = {av, av, av, av}, b[2] = {bv, bv};
    mma16816(d, a, b);
    bool ok = (d[0] == 24.f) && (d[1] == 24.f) && (d[2] == 24.f) && (d[3] == 24.f);
    ok = __all_sync(0xffffffffu, ok);
    if (threadIdx.x == 0) g_mma_ok = ok ? 1 : 0;
}

// ---------------- setup kernels --------------------------------------------
__global__ void zero_k() {
    int i = blockIdx.x * blockDim.x + threadIdx.x;
    if (i < C_IN)    { g_colsum[i] = 0.f; g_colsum2[i] = 0.f; }
    if (i < N_NODES) { g_deg[i] = 0; }
    if (i == 0)      { g_flag32 = 0; }
}

__global__ void detect_k(const long long* __restrict__ ei) {
    int i = blockIdx.x * blockDim.x + threadIdx.x;
    if (i < N_EDGES) {
        long long v = ei[i];
        if (v < 0 || v >= N_NODES) atomicOr(&g_flag32, 1);
    }
}

__global__ void convert_k(const void* __restrict__ ei) {
    int i = blockIdx.x * blockDim.x + threadIdx.x;
    if (i >= 2 * N_EDGES) return;
    g_ei32[i] = g_flag32 ? ((const int*)ei)[i]
                         : (int)((const long long*)ei)[i];
}

__global__ void colstats_k(const float* __restrict__ x) {
    int col = blockIdx.x * 256 + threadIdx.x;
    int r0  = blockIdx.y * 250;
    float s = 0.f, s2 = 0.f;
    for (int r = r0; r < r0 + 250; r++) {
        float v = x[(size_t)r * C_IN + col];
        s += v; s2 += v * v;
    }
    atomicAdd(&g_colsum[col], s);
    atomicAdd(&g_colsum2[col], s2);
}

__global__ void stats_k(const float* __restrict__ w, const float* __restrict__ b,
                        const float* __restrict__ ms) {
    int j = blockIdx.x * blockDim.x + threadIdx.x;
    if (j >= C_IN) return;
    float m   = g_colsum[j]  * (1.f / N_NODES);
    float ex2 = g_colsum2[j] * (1.f / N_NODES);
    float s   = ms[j];
    float var = ex2 - 2.f * s * m * m + s * s * m * m;
    float Aj  = rsqrtf(var + 1e-5f) * w[j];
    g_A[j] = Aj;
    g_B[j] = b[j] - s * m * Aj;
}

__global__ void deg_k() {
    int e = blockIdx.x * blockDim.x + threadIdx.x;
    if (e < N_EDGES) atomicAdd(&g_deg[g_ei32[N_EDGES + e]], 1);
}

__global__ void dis_k() {
    int i = blockIdx.x * blockDim.x + threadIdx.x;
    if (i < N_NODES) g_dis[i] = rsqrtf((float)g_deg[i] + 1.0f);
}

__global__ void xnorm_k(const float* __restrict__ x) {
    int i = blockIdx.x * blockDim.x + threadIdx.x;
    int row = i >> 8;
    if (row >= N_NODES) return;
    int c4 = i & 255;
    float4 xv = ((const float4*)x)[i];
    float4 Av = ((const float4*)g_A)[c4];
    float4 Bv = ((const float4*)g_B)[c4];
    float4 o;
    o.x = fmaf(xv.x, Av.x, Bv.x);
    o.y = fmaf(xv.y, Av.y, Bv.y);
    o.z = fmaf(xv.z, Av.z, Bv.z);
    o.w = fmaf(xv.w, Av.w, Bv.w);
    ((float4*)g_xnorm)[i] = o;
    float dd = g_dis[row]; dd *= dd;
    ((float4*)g_sx)[i] = make_float4(dd * o.x, dd * o.y, dd * o.z, dd * o.w);
}

// Edge-parallel SpMM: out[dst] += dis[src]*dis[dst] * feat[src]
template<int PH>
__global__ __launch_bounds__(256) void spmm_k() {
    const float* __restrict__ feat = (PH == 0) ? g_xnorm : g_h;
    float* __restrict__ out        = (PH == 0) ? g_sx    : g_sh;
    int t = threadIdx.x;
    #pragma unroll 1
    for (int it = 0; it < 8; it++) {
        int e = blockIdx.x * 8 + it;
        int s = g_ei32[e];
        int d = g_ei32[N_EDGES + e];
        float w = g_dis[s] * g_dis[d];
        float4 v = ((const float4*)(feat + (size_t)s * 1024))[t];
        float* dst = out + (size_t)d * 1024 + t * 4;
        asm volatile("red.global.add.v4.f32 [%0], {%1,%2,%3,%4};"
                     :: "l"(dst), "f"(w * v.x), "f"(w * v.y),
                        "f"(w * v.z), "f"(w * v.w) : "memory");
    }
}

// ---------------- B conversion: fp32 W [k][n] -> g_bh [n][3072] [hi,hi,lo] ---
// MODE 0: p0 = W1 (ld 1024).  MODE 1: n<512 -> Wm[k][n], else Ws[k][n-512].
template<int MODE>
__global__ void convB_k(const float* __restrict__ p0, const float* __restrict__ p1) {
    __shared__ float t[32][33];
    int n0 = blockIdx.x * 32, k0 = blockIdx.y * 32;
    int tx = threadIdx.x, ty = threadIdx.y;         // block (32, 8)
    #pragma unroll
    for (int j = 0; j < 32; j += 8) {
        int k = k0 + ty + j, n = n0 + tx;
        float v;
        if (MODE == 0) v = p0[(size_t)k * 1024 + n];
        else           v = (n < 512) ? p0[(size_t)k * 512 + n]
                                     : p1[(size_t)k * 512 + (n - 512)];
        t[ty + j][tx] = v;
    }
    __syncthreads();
    #pragma unroll
    for (int j = 0; j < 32; j += 8) {
        int n = n0 + ty + j, k = k0 + tx;
        float v = t[tx][ty + j];
        __nv_bfloat16 h = __float2bfloat16(v);
        __nv_bfloat16 l = __float2bfloat16(v - __bfloat162float(h));
        size_t b = (size_t)n * KP + k;
        g_bh[b]        = h;
        g_bh[b + 1024] = h;
        g_bh[b + 2048] = l;
    }
}

// ---------------- mma.sync bf16 GEMM (guarded by g_mma_ok == 1) -------------
// CTA 128x128, 8 warps (4M x 2N), warp tile 32x64, BK=32 bf16 per chunk.
// A split hi/lo computed in-kernel from fp32 (segments [hi,lo,hi] over K'=3072).
#define ROWB 40
#define NCH  (KP / 32)        // 96 chunks

// load 8 fp32, convert to 8 bf16 (hi, or lo residual), packed as uint4
__device__ __forceinline__ uint4 ldcvtA(const float* p, int lo) {
    float4 x = *(const float4*)p;
    float4 y = *(const float4*)(p + 4);
    __nv_bfloat162 h0 = __floats2bfloat162_rn(x.x, x.y);
    __nv_bfloat162 h1 = __floats2bfloat162_rn(x.z, x.w);
    __nv_bfloat162 h2 = __floats2bfloat162_rn(y.x, y.y);
    __nv_bfloat162 h3 = __floats2bfloat162_rn(y.z, y.w);
    if (lo) {
        h0 = __floats2bfloat162_rn(x.x - __low2float(h0), x.y - __high2float(h0));
        h1 = __floats2bfloat162_rn(x.z - __low2float(h1), x.w - __high2float(h1));
        h2 = __floats2bfloat162_rn(y.x - __low2float(h2), y.y - __high2float(h2));
        h3 = __floats2bfloat162_rn(y.z - __low2float(h3), y.w - __high2float(h3));
    }
    uint4 r;
    r.x = *(uint32_t*)&h0; r.y = *(uint32_t*)&h1;
    r.z = *(uint32_t*)&h2; r.w = *(uint32_t*)&h3;
    return r;
}

template<int MODE>
__global__ void __launch_bounds__(256) gemm_mma(const float* __restrict__ bias0,
                                                const float* __restrict__ bias1,
                                                float* __restrict__ outp) {
    if (g_mma_ok == 0) return;
    __shared__ __align__(16) __nv_bfloat16 sA[2][128 * ROWB];
    __shared__ __align__(16) __nv_bfloat16 sB[2][128 * ROWB];

    const float* __restrict__ Ap = (MODE == 0) ? g_sx : g_sh;
    int tid  = threadIdx.x;
    int lane = tid & 31, w = tid >> 5;
    int wm = w >> 1, wn = w & 1;
    int g = lane >> 2, tig = lane & 3;
    int row0 = blockIdx.y * 128, col0 = blockIdx.x * 128;

    // global->smem mapping: each thread owns rows r0, r0+64; 16B bf16 segment
    int r0 = tid >> 2;                 // [0,64)
    int u0b = (tid & 3) * 16;          // byte offset in 64B bf16 chunk row
    int kl  = (tid & 3) * 8;           // fp32 element offset (8 floats per seg)
    int r1 = r0 + 64;
    int ra0 = row0 + r0; if (ra0 >= N_NODES) ra0 = N_NODES - 1;
    int ra1 = row0 + r1; if (ra1 >= N_NODES) ra1 = N_NODES - 1;
    const float* srcA0f = Ap + (size_t)ra0 * 1024 + kl;
    const float* srcA1f = Ap + (size_t)ra1 * 1024 + kl;
    const char* srcB0 = (const char*)(g_bh + (size_t)(col0 + r0) * KP) + u0b;
    const char* srcB1 = (const char*)(g_bh + (size_t)(col0 + r1) * KP) + u0b;
    int dst0 = r0 * 80 + u0b;
    int dst1 = r1 * 80 + u0b;

    float acc[2][8][4];
    #pragma unroll
    for (int m = 0; m < 2; m++)
        #pragma unroll
        for (int n = 0; n < 8; n++)
            #pragma unroll
            for (int q = 0; q < 4; q++) acc[m][n][q] = 0.f;

    // prologue: chunk 0 (seg 0 = hi) -> buffer 0
    {
        uint4 ua0 = ldcvtA(srcA0f, 0);
        uint4 ua1 = ldcvtA(srcA1f, 0);
        float4 vb0 = *(const float4*)srcB0;
        float4 vb1 = *(const float4*)srcB1;
        *(uint4*)((char*)&sA[0][0] + dst0)  = ua0;
        *(uint4*)((char*)&sA[0][0] + dst1)  = ua1;
        *(float4*)((char*)&sB[0][0] + dst0) = vb0;
        *(float4*)((char*)&sB[0][0] + dst1) = vb1;
    }
    __syncthreads();

    // fragment base byte offsets (A elem (m,k): byte m*80 + k*2)
    int aoff = (wm * 32 + g) * 80 + tig * 4;
    int boff = (wn * 64 + g) * 80 + tig * 4;

    #pragma unroll 1
    for (int c = 0; c < NCH; c++) {
        int b = c & 1;
        bool more = (c + 1 < NCH);
        uint4 ua0, ua1; float4 vb0, vb1;
        if (more) {
            int cn = c + 1;
            int seg = cn >> 5;                       // 0:hi 1:lo 2:hi
            int kk  = (cn & 31) * 32;                // underlying fp32 k base
            ua0 = ldcvtA(srcA0f + kk, seg == 1);
            ua1 = ldcvtA(srcA1f + kk, seg == 1);
            vb0 = *(const float4*)(srcB0 + (size_t)cn * 64);
            vb1 = *(const float4*)(srcB1 + (size_t)cn * 64);
        }
        const char* aB = (const char*)&sA[b][0];
        const char* bB = (const char*)&sB[b][0];
        #pragma unroll
        for (int kt = 0; kt < 2; kt++) {
            uint32_t af[2][4];
            #pragma unroll
            for (int mt = 0; mt < 2; mt++) {
                const char* p = aB + aoff + mt * (16 * 80) + kt * 32;
                af[mt][0] = *(const uint32_t*)(p);
                af[mt][1] = *(const uint32_t*)(p + 640);
                af[mt][2] = *(const uint32_t*)(p + 16);
                af[mt][3] = *(const uint32_t*)(p + 656);
            }
            #pragma unroll
            for (int np = 0; np < 4; np++) {
                const char* p = bB + boff + np * (16 * 80) + kt * 32;
                uint32_t bq[4];
                bq[0] = *(const uint32_t*)(p);
                bq[1] = *(const uint32_t*)(p + 16);
                bq[2] = *(const uint32_t*)(p + 640);
                bq[3] = *(const uint32_t*)(p + 656);
                #pragma unroll
                for (int mt = 0; mt < 2; mt++) {
                    mma16816(acc[mt][np * 2],     af[mt], bq);
                    mma16816(acc[mt][np * 2 + 1], af[mt], bq + 2);
                }
            }
        }
        if (more) {
            int nb = b ^ 1;
            *(uint4*)((char*)&sA[nb][0] + dst0)  = ua0;
            *(uint4*)((char*)&sA[nb][0] + dst1)  = ua1;
            *(float4*)((char*)&sB[nb][0] + dst0) = vb0;
            *(float4*)((char*)&sB[nb][0] + dst1) = vb1;
        }
        __syncthreads();
    }

    // ---- epilogue ----
    #pragma unroll
    for (int mt = 0; mt < 2; mt++) {
        int rlo = row0 + wm * 32 + mt * 16 + g;
        #pragma unroll
        for (int half = 0; half < 2; half++) {
            int row = rlo + half * 8;
            if (row >= N_NODES) continue;
            float dd = 0.f;
            if (MODE == 0) { dd = g_dis[row]; dd *= dd; }
            #pragma unroll
            for (int nt = 0; nt < 8; nt++) {
                int cca = col0 + wn * 64 + nt * 8 + tig * 2;
                float b0, b1v;
                if (MODE == 0) { b0 = __ldg(&bias0[cca]); b1v = __ldg(&bias0[cca + 1]); }
                else if (cca < 512) { b0 = __ldg(&bias0[cca]); b1v = __ldg(&bias0[cca + 1]); }
                else { b0 = __ldg(&bias1[cca - 512]); b1v = __ldg(&bias1[cca - 511]); }
                float v0 = acc[mt][nt][half * 2]     + b0;
                float v1 = acc[mt][nt][half * 2 + 1] + b1v;
                if (MODE == 0) {
                    v0 = (v0 > 0.f) ? v0 : 0.1f * v0;
                    v1 = (v1 > 0.f) ? v1 : 0.1f * v1;
                    *(float2*)&g_h [(size_t)row * 1024 + cca] = make_float2(v0, v1);
                    *(float2*)&g_sh[(size_t)row * 1024 + cca] = make_float2(dd * v0, dd * v1);
                } else {
                    if (cca < C_OUT) {
                        *(float2*)&outp[(size_t)row * C_OUT + cca]        = make_float2(v0, v1);
                        *(float2*)&outp[NOUT + (size_t)row * C_OUT + cca] = make_float2(v0, v1);
                    } else {
                        *(float2*)&outp[2 * NOUT + (size_t)row * C_OUT + (cca - C_OUT)]
                            = make_float2(v0, v1);
                    }
                }
            }
        }
    }
}

// ---------------- FFMA fallback GEMM (guarded by g_mma_ok == 0) -------------
// Proven R1 kernel, adapted only for split (Wm,Ws)/(bm,bs) operands.
#define BM 128
#define BN 128
#define BK 16

template<int MODE>
__global__ __launch_bounds__(256) void gemm_ffma(const float* __restrict__ p0,
                                                 const float* __restrict__ p1,
                                                 const float* __restrict__ bias0,
                                                 const float* __restrict__ bias1,
                                                 float* __restrict__ outp) {
    if (g_mma_ok != 0) return;
    const float* __restrict__ Ap = (MODE == 0) ? g_sx : g_sh;
    const int M = N_NODES, K = 1024;

    int col0 = blockIdx.x * BN;
    const float* Bp; int ldB, bcol;
    if (MODE == 0) { Bp = p0; ldB = 1024; bcol = col0; }
    else {
        ldB = 512;
        if (col0 < 512) { Bp = p0; bcol = col0; }
        else            { Bp = p1; bcol = col0 - 512; }
    }

    __shared__ float As[2][BK * BM];
    __shared__ float Bs[2][BK * BN];

    int tid  = threadIdx.x;
    int row0 = blockIdx.y * BM;
    int tx = tid & 15, ty = tid >> 4;

    int ar0 = tid >> 2,  ak = (tid & 3) << 2;
    int ar1 = ar0 + 64;
    int br0 = tid >> 5,  bq = (tid & 31) << 2;
    int br1 = br0 + 8;

    const float4 z4 = make_float4(0.f, 0.f, 0.f, 0.f);
    float4 la0, la1, lb0, lb1;

    la0 = (row0 + ar0 < M) ? *(const float4*)(Ap + (size_t)(row0 + ar0) * K + ak) : z4;
    la1 = (row0 + ar1 < M) ? *(const float4*)(Ap + (size_t)(row0 + ar1) * K + ak) : z4;
    lb0 = *(const float4*)(Bp + (size_t)br0 * ldB + bcol + bq);
    lb1 = *(const float4*)(Bp + (size_t)br1 * ldB + bcol + bq);
    As[0][(ak + 0) * BM + ar0] = la0.x; As[0][(ak + 1) * BM + ar0] = la0.y;
    As[0][(ak + 2) * BM + ar0] = la0.z; As[0][(ak + 3) * BM + ar0] = la0.w;
    As[0][(ak + 0) * BM + ar1] = la1.x; As[0][(ak + 1) * BM + ar1] = la1.y;
    As[0][(ak + 2) * BM + ar1] = la1.z; As[0][(ak + 3) * BM + ar1] = la1.w;
    *(float4*)&Bs[0][br0 * BN + bq] = lb0;
    *(float4*)&Bs[0][br1 * BN + bq] = lb1;
    __syncthreads();

    float acc[8][8];
    #pragma unroll
    for (int i = 0; i < 8; i++)
        #pragma unroll
        for (int j = 0; j < 8; j++) acc[i][j] = 0.f;

    const int KT = K / BK;
    for (int kt = 0; kt < KT; kt++) {
        int cur = kt & 1;
        if (kt + 1 < KT) {
            int k0 = (kt + 1) * BK;
            la0 = (row0 + ar0 < M) ? *(const float4*)(Ap + (size_t)(row0 + ar0) * K + k0 + ak) : z4;
            la1 = (row0 + ar1 < M) ? *(const float4*)(Ap + (size_t)(row0 + ar1) * K + k0 + ak) : z4;
            lb0 = *(const float4*)(Bp + (size_t)(k0 + br0) * ldB + bcol + bq);
            lb1 = *(const float4*)(Bp + (size_t)(k0 + br1) * ldB + bcol + bq);
        }
        #pragma unroll
        for (int k = 0; k < BK; k++) {
            float ra[8], rb[8];
            *(float4*)&ra[0] = *(const float4*)&As[cur][k * BM + ty * 8];
            *(float4*)&ra[4] = *(const float4*)&As[cur][k * BM + ty * 8 + 4];
            *(float4*)&rb[0] = *(const float4*)&Bs[cur][k * BN + tx * 8];
            *(float4*)&rb[4] = *(const float4*)&Bs[cur][k * BN + tx * 8 + 4];
            #pragma unroll
            for (int i = 0; i < 8; i++)
                #pragma unroll
                for (int j = 0; j < 8; j++)
                    acc[i][j] = fmaf(ra[i], rb[j], acc[i][j]);
        }
        if (kt + 1 < KT) {
            int nb = cur ^ 1;
            As[nb][(ak + 0) * BM + ar0] = la0.x; As[nb][(ak + 1) * BM + ar0] = la0.y;
            As[nb][(ak + 2) * BM + ar0] = la0.z; As[nb][(ak + 3) * BM + ar0] = la0.w;
            As[nb][(ak + 0) * BM + ar1] = la1.x; As[nb][(ak + 1) * BM + ar1] = la1.y;
            As[nb][(ak + 2) * BM + ar1] = la1.z; As[nb][(ak + 3) * BM + ar1] = la1.w;
            *(float4*)&Bs[nb][br0 * BN + bq] = lb0;
            *(float4*)&Bs[nb][br1 * BN + bq] = lb1;
        }
        __syncthreads();
    }

    #pragma unroll
    for (int i = 0; i < 8; i++) {
        int r = row0 + ty * 8 + i;
        if (r >= M) continue;
        float dd = 0.f;
        if (MODE == 0) { dd = g_dis[r]; dd *= dd; }
        #pragma unroll
        for (int j = 0; j < 8; j++) {
            int c = col0 + tx * 8 + j;
            float bv = (MODE == 0) ? bias0[c]
                     : (c < 512 ? bias0[c] : bias1[c - 512]);
            float v = acc[i][j] + bv;
            if (MODE == 0) {
                v = (v > 0.f) ? v : 0.1f * v;
                g_h [(size_t)r * 1024 + c] = v;
                g_sh[(size_t)r * 1024 + c] = dd * v;
            } else {
                if (c < C_OUT) {
                    outp[(size_t)r * C_OUT + c]        = v;
                    outp[NOUT + (size_t)r * C_OUT + c] = v;
                } else {
                    outp[2 * NOUT + (size_t)r * C_OUT + (c - C_OUT)] = v;
                }
            }
        }
    }
}

// ---------------- launcher --------------------------------------------------
extern "C" void kernel_launch(void* const* d_in, const int* in_sizes, int n_in,
                              void* d_out, int out_size) {
    const float* x   = (const float*)d_in[0];
    const void*  ei  = d_in[1];
    const float* W1  = (const float*)d_in[2];
    const float* b1  = (const float*)d_in[3];
    const float* Wm  = (const float*)d_in[4];
    const float* bm  = (const float*)d_in[5];
    const float* Ws  = (const float*)d_in[6];
    const float* bs  = (const float*)d_in[7];
    const float* gw  = (const float*)d_in[8];
    const float* gb  = (const float*)d_in[9];
    const float* gms = (const float*)d_in[10];
    float* out = (float*)d_out;

    dim3 gg(1024 / 128, (N_NODES + 127) / 128);   // (8, 79)

    zero_k   <<<40, 256>>>();
    canary_k <<<1, 32>>>();
    detect_k <<<(N_EDGES + 255) / 256, 256>>>((const long long*)ei);
    convert_k<<<(2 * N_EDGES + 255) / 256, 256>>>(ei);
    colstats_k<<<dim3(4, 40), 256>>>(x);
    stats_k  <<<4, 256>>>(gw, gb, gms);
    deg_k    <<<(N_EDGES + 255) / 256, 256>>>();
    dis_k    <<<(N_NODES + 255) / 256, 256>>>();
    xnorm_k  <<<(N_NODES * C_IN / 4 + 255) / 256, 256>>>(x);
    convB_k<0><<<dim3(32, 32), dim3(32, 8)>>>(W1, nullptr);
    spmm_k<0><<<N_EDGES / 8, 256>>>();
    gemm_mma<0> <<<gg, 256>>>(b1, nullptr, nullptr);
    gemm_ffma<0><<<gg, 256>>>(W1, nullptr, b1, nullptr, nullptr);
    spmm_k<1><<<N_EDGES / 8, 256>>>();
    convB_k<1><<<dim3(32, 32), dim3(32, 8)>>>(Wm, Ws);
    gemm_mma<1> <<<gg, 256>>>(bm, bs, out);
    gemm_ffma<1><<<gg, 256>>>(Wm, Ws, bm, bs, out);
}

// round 6
// speedup vs baseline: 1.9047x; 1.1604x over previous
#include <cuda_runtime.h>
#include <cuda_bf16.h>
#include <cstdint>

#define N_NODES 10000
#define N_EDGES 160000
#define C_IN    1024
#define C_OUT   512
#define KP      3072                       // 3-way split K'
#define NOUT    ((size_t)N_NODES * C_OUT)

// ---------------- scratch (static device globals; no allocations) ----------
__device__ float g_xnorm[(size_t)N_NODES * C_IN];
__device__ float g_sx   [(size_t)N_NODES * C_IN];
__device__ float g_h    [(size_t)N_NODES * 1024];
__device__ float g_sh   [(size_t)N_NODES * 1024];
__device__ float g_colsum [C_IN];
__device__ float g_colsum2[C_IN];
__device__ float g_A[C_IN];
__device__ float g_B[C_IN];
__device__ float g_dis[N_NODES];
__device__ int   g_deg[N_NODES];
__device__ int   g_ei32[2 * N_EDGES];
__device__ int   g_flag32;
// CSR by destination
__device__ int   g_rowptr[N_NODES + 1];
__device__ int   g_cursor[N_NODES];
__device__ int   g_esrc[N_EDGES];
__device__ float g_ew  [N_EDGES];
// bf16 B operand [n][k'] with K-segments [hi, hi, lo]  (6.3 MB)
__device__ __nv_bfloat16 g_bh[(size_t)1024 * KP];

// ---------------- mma helper -------------------------------------------------
__device__ __forceinline__ void mma16816(float* d, const uint32_t* a, const uint32_t* b) {
    asm volatile(
        "mma.sync.aligned.m16n8k16.row.col.f32.bf16.bf16.f32 "
        "{%0,%1,%2,%3}, {%4,%5,%6,%7}, {%8,%9}, {%0,%1,%2,%3};"
        : "+f"(d[0]), "+f"(d[1]), "+f"(d[2]), "+f"(d[3])
        : "r"(a[0]), "r"(a[1]), "r"(a[2]), "r"(a[3]), "r"(b[0]), "r"(b[1]));
}

// ---------------- setup kernels --------------------------------------------
__global__ void zero_k() {
    int i = blockIdx.x * blockDim.x + threadIdx.x;
    if (i < C_IN)    { g_colsum[i] = 0.f; g_colsum2[i] = 0.f; }
    if (i < N_NODES) { g_deg[i] = 0; }
    if (i == 0)      { g_flag32 = 0; }
}

__global__ void detect_k(const long long* __restrict__ ei) {
    int i = blockIdx.x * blockDim.x + threadIdx.x;
    if (i < N_EDGES) {
        long long v = ei[i];
        if (v < 0 || v >= N_NODES) atomicOr(&g_flag32, 1);
    }
}

__global__ void convert_k(const void* __restrict__ ei) {
    int i = blockIdx.x * blockDim.x + threadIdx.x;
    if (i >= 2 * N_EDGES) return;
    g_ei32[i] = g_flag32 ? ((const int*)ei)[i]
                         : (int)((const long long*)ei)[i];
}

__global__ void colstats_k(const float* __restrict__ x) {
    int col = blockIdx.x * 256 + threadIdx.x;
    int r0  = blockIdx.y * 250;
    float s = 0.f, s2 = 0.f;
    for (int r = r0; r < r0 + 250; r++) {
        float v = x[(size_t)r * C_IN + col];
        s += v; s2 += v * v;
    }
    atomicAdd(&g_colsum[col], s);
    atomicAdd(&g_colsum2[col], s2);
}

__global__ void stats_k(const float* __restrict__ w, const float* __restrict__ b,
                        const float* __restrict__ ms) {
    int j = blockIdx.x * blockDim.x + threadIdx.x;
    if (j >= C_IN) return;
    float m   = g_colsum[j]  * (1.f / N_NODES);
    float ex2 = g_colsum2[j] * (1.f / N_NODES);
    float s   = ms[j];
    float var = ex2 - 2.f * s * m * m + s * s * m * m;
    float Aj  = rsqrtf(var + 1e-5f) * w[j];
    g_A[j] = Aj;
    g_B[j] = b[j] - s * m * Aj;
}

__global__ void deg_k() {
    int e = blockIdx.x * blockDim.x + threadIdx.x;
    if (e < N_EDGES) atomicAdd(&g_deg[g_ei32[N_EDGES + e]], 1);
}

__global__ void dis_k() {
    int i = blockIdx.x * blockDim.x + threadIdx.x;
    if (i < N_NODES) g_dis[i] = rsqrtf((float)g_deg[i] + 1.0f);
}

// Single-block exclusive scan of g_deg -> g_rowptr / g_cursor (1024 thr x 10)
__global__ void scan_k() {
    __shared__ int ps[1024];
    int t = threadIdx.x;
    int base = t * 10;
    int loc[10];
    int sum = 0;
    #pragma unroll
    for (int i = 0; i < 10; i++) {
        int idx = base + i;
        int v = (idx < N_NODES) ? g_deg[idx] : 0;
        loc[i] = sum;              // exclusive within chunk
        sum += v;
    }
    ps[t] = sum;
    __syncthreads();
    // Hillis-Steele inclusive scan
    for (int off = 1; off < 1024; off <<= 1) {
        int v = (t >= off) ? ps[t - off] : 0;
        __syncthreads();
        ps[t] += v;
        __syncthreads();
    }
    int excl = ps[t] - sum;
    #pragma unroll
    for (int i = 0; i < 10; i++) {
        int idx = base + i;
        if (idx < N_NODES) {
            int p = excl + loc[i];
            g_rowptr[idx] = p;
            g_cursor[idx] = p;
        }
    }
    if (t == 1023) g_rowptr[N_NODES] = ps[1023];
}

__global__ void scatter_k() {
    int e = blockIdx.x * blockDim.x + threadIdx.x;
    if (e >= N_EDGES) return;
    int s = g_ei32[e];
    int d = g_ei32[N_EDGES + e];
    int pos = atomicAdd(&g_cursor[d], 1);
    g_esrc[pos] = s;
    g_ew[pos]   = g_dis[s] * g_dis[d];
}

__global__ void xnorm_k(const float* __restrict__ x) {
    int i = blockIdx.x * blockDim.x + threadIdx.x;
    if (i >= N_NODES * 256) return;
    int c4 = i & 255;
    float4 xv = ((const float4*)x)[i];
    float4 Av = ((const float4*)g_A)[c4];
    float4 Bv = ((const float4*)g_B)[c4];
    float4 o;
    o.x = fmaf(xv.x, Av.x, Bv.x);
    o.y = fmaf(xv.y, Av.y, Bv.y);
    o.z = fmaf(xv.z, Av.z, Bv.z);
    o.w = fmaf(xv.w, Av.w, Bv.w);
    ((float4*)g_xnorm)[i] = o;
}

// CSR pull SpMM: out[d] = dis[d]^2 * feat[d] + sum_{e: dst=d} w_e * feat[src_e]
// One block per dst row; 256 threads, one float4 column each.
template<int PH>
__global__ __launch_bounds__(256) void spmm_pull() {
    const float4* __restrict__ feat = (const float4*)((PH == 0) ? g_xnorm : g_h);
    float4* __restrict__ out        = (float4*)((PH == 0) ? g_sx : g_sh);
    int d = blockIdx.x;
    int t = threadIdx.x;
    int beg = g_rowptr[d], end = g_rowptr[d + 1];
    float dd = g_dis[d]; dd *= dd;
    float4 v0 = feat[(size_t)d * 256 + t];
    float4 acc = make_float4(dd * v0.x, dd * v0.y, dd * v0.z, dd * v0.w);
    int   sn = (beg < end) ? __ldg(&g_esrc[beg]) : 0;
    float wn = (beg < end) ? __ldg(&g_ew[beg])   : 0.f;
    for (int j = beg; j < end; j++) {
        int s = sn; float w = wn;
        if (j + 1 < end) { sn = __ldg(&g_esrc[j + 1]); wn = __ldg(&g_ew[j + 1]); }
        float4 v = feat[(size_t)s * 256 + t];
        acc.x = fmaf(w, v.x, acc.x);
        acc.y = fmaf(w, v.y, acc.y);
        acc.z = fmaf(w, v.z, acc.z);
        acc.w = fmaf(w, v.w, acc.w);
    }
    out[(size_t)d * 256 + t] = acc;
}

// ---------------- B conversion: fp32 W [k][n] -> g_bh [n][3072] [hi,hi,lo] ---
template<int MODE>
__global__ void convB_k(const float* __restrict__ p0, const float* __restrict__ p1) {
    __shared__ float t[32][33];
    int n0 = blockIdx.x * 32, k0 = blockIdx.y * 32;
    int tx = threadIdx.x, ty = threadIdx.y;         // block (32, 8)
    #pragma unroll
    for (int j = 0; j < 32; j += 8) {
        int k = k0 + ty + j, n = n0 + tx;
        float v;
        if (MODE == 0) v = p0[(size_t)k * 1024 + n];
        else           v = (n < 512) ? p0[(size_t)k * 512 + n]
                                     : p1[(size_t)k * 512 + (n - 512)];
        t[ty + j][tx] = v;
    }
    __syncthreads();
    #pragma unroll
    for (int j = 0; j < 32; j += 8) {
        int n = n0 + ty + j, k = k0 + tx;
        float v = t[tx][ty + j];
        __nv_bfloat16 h = __float2bfloat16(v);
        __nv_bfloat16 l = __float2bfloat16(v - __bfloat162float(h));
        size_t b = (size_t)n * KP + k;
        g_bh[b]        = h;
        g_bh[b + 1024] = h;
        g_bh[b + 2048] = l;
    }
}

// ---------------- mma.sync bf16 GEMM -----------------------------------------
// CTA 128x128, 8 warps (4M x 2N), warp tile 32x64, BK=32 bf16 per chunk.
// A split hi/lo computed in-kernel from fp32 (segments [hi,lo,hi] over K'=3072).
#define ROWB 40
#define NCH  (KP / 32)        // 96 chunks

__device__ __forceinline__ uint4 ldcvtA(const float* p, int lo) {
    float4 x = *(const float4*)p;
    float4 y = *(const float4*)(p + 4);
    __nv_bfloat162 h0 = __floats2bfloat162_rn(x.x, x.y);
    __nv_bfloat162 h1 = __floats2bfloat162_rn(x.z, x.w);
    __nv_bfloat162 h2 = __floats2bfloat162_rn(y.x, y.y);
    __nv_bfloat162 h3 = __floats2bfloat162_rn(y.z, y.w);
    if (lo) {
        h0 = __floats2bfloat162_rn(x.x - __low2float(h0), x.y - __high2float(h0));
        h1 = __floats2bfloat162_rn(x.z - __low2float(h1), x.w - __high2float(h1));
        h2 = __floats2bfloat162_rn(y.x - __low2float(h2), y.y - __high2float(h2));
        h3 = __floats2bfloat162_rn(y.z - __low2float(h3), y.w - __high2float(h3));
    }
    uint4 r;
    r.x = *(uint32_t*)&h0; r.y = *(uint32_t*)&h1;
    r.z = *(uint32_t*)&h2; r.w = *(uint32_t*)&h3;
    return r;
}

template<int MODE>
__global__ void __launch_bounds__(256) gemm_mma(const float* __restrict__ bias0,
                                                const float* __restrict__ bias1,
                                                float* __restrict__ outp) {
    __shared__ __align__(16) __nv_bfloat16 sA[2][128 * ROWB];
    __shared__ __align__(16) __nv_bfloat16 sB[2][128 * ROWB];

    const float* __restrict__ Ap = (MODE == 0) ? g_sx : g_sh;
    int tid  = threadIdx.x;
    int lane = tid & 31, w = tid >> 5;
    int wm = w >> 1, wn = w & 1;
    int g = lane >> 2, tig = lane & 3;
    int row0 = blockIdx.y * 128, col0 = blockIdx.x * 128;

    int r0 = tid >> 2;
    int u0b = (tid & 3) * 16;
    int kl  = (tid & 3) * 8;
    int r1 = r0 + 64;
    int ra0 = row0 + r0; if (ra0 >= N_NODES) ra0 = N_NODES - 1;
    int ra1 = row0 + r1; if (ra1 >= N_NODES) ra1 = N_NODES - 1;
    const float* srcA0f = Ap + (size_t)ra0 * 1024 + kl;
    const float* srcA1f = Ap + (size_t)ra1 * 1024 + kl;
    const char* srcB0 = (const char*)(g_bh + (size_t)(col0 + r0) * KP) + u0b;
    const char* srcB1 = (const char*)(g_bh + (size_t)(col0 + r1) * KP) + u0b;
    int dst0 = r0 * 80 + u0b;
    int dst1 = r1 * 80 + u0b;

    float acc[2][8][4];
    #pragma unroll
    for (int m = 0; m < 2; m++)
        #pragma unroll
        for (int n = 0; n < 8; n++)
            #pragma unroll
            for (int q = 0; q < 4; q++) acc[m][n][q] = 0.f;

    {
        uint4 ua0 = ldcvtA(srcA0f, 0);
        uint4 ua1 = ldcvtA(srcA1f, 0);
        float4 vb0 = *(const float4*)srcB0;
        float4 vb1 = *(const float4*)srcB1;
        *(uint4*)((char*)&sA[0][0] + dst0)  = ua0;
        *(uint4*)((char*)&sA[0][0] + dst1)  = ua1;
        *(float4*)((char*)&sB[0][0] + dst0) = vb0;
        *(float4*)((char*)&sB[0][0] + dst1) = vb1;
    }
    __syncthreads();

    int aoff = (wm * 32 + g) * 80 + tig * 4;
    int boff = (wn * 64 + g) * 80 + tig * 4;

    #pragma unroll 1
    for (int c = 0; c < NCH; c++) {
        int b = c & 1;
        bool more = (c + 1 < NCH);
        uint4 ua0, ua1; float4 vb0, vb1;
        if (more) {
            int cn = c + 1;
            int seg = cn >> 5;                       // 0:hi 1:lo 2:hi
            int kk  = (cn & 31) * 32;
            ua0 = ldcvtA(srcA0f + kk, seg == 1);
            ua1 = ldcvtA(srcA1f + kk, seg == 1);
            vb0 = *(const float4*)(srcB0 + (size_t)cn * 64);
            vb1 = *(const float4*)(srcB1 + (size_t)cn * 64);
        }
        const char* aB = (const char*)&sA[b][0];
        const char* bB = (const char*)&sB[b][0];
        #pragma unroll
        for (int kt = 0; kt < 2; kt++) {
            uint32_t af[2][4];
            #pragma unroll
            for (int mt = 0; mt < 2; mt++) {
                const char* p = aB + aoff + mt * (16 * 80) + kt * 32;
                af[mt][0] = *(const uint32_t*)(p);
                af[mt][1] = *(const uint32_t*)(p + 640);
                af[mt][2] = *(const uint32_t*)(p + 16);
                af[mt][3] = *(const uint32_t*)(p + 656);
            }
            #pragma unroll
            for (int np = 0; np < 4; np++) {
                const char* p = bB + boff + np * (16 * 80) + kt * 32;
                uint32_t bq[4];
                bq[0] = *(const uint32_t*)(p);
                bq[1] = *(const uint32_t*)(p + 16);
                bq[2] = *(const uint32_t*)(p + 640);
                bq[3] = *(const uint32_t*)(p + 656);
                #pragma unroll
                for (int mt = 0; mt < 2; mt++) {
                    mma16816(acc[mt][np * 2],     af[mt], bq);
                    mma16816(acc[mt][np * 2 + 1], af[mt], bq + 2);
                }
            }
        }
        if (more) {
            int nb = b ^ 1;
            *(uint4*)((char*)&sA[nb][0] + dst0)  = ua0;
            *(uint4*)((char*)&sA[nb][0] + dst1)  = ua1;
            *(float4*)((char*)&sB[nb][0] + dst0) = vb0;
            *(float4*)((char*)&sB[nb][0] + dst1) = vb1;
        }
        __syncthreads();
    }

    // ---- epilogue ----
    #pragma unroll
    for (int mt = 0; mt < 2; mt++) {
        int rlo = row0 + wm * 32 + mt * 16 + g;
        #pragma unroll
        for (int half = 0; half < 2; half++) {
            int row = rlo + half * 8;
            if (row >= N_NODES) continue;
            #pragma unroll
            for (int nt = 0; nt < 8; nt++) {
                int cca = col0 + wn * 64 + nt * 8 + tig * 2;
                float b0, b1v;
                if (MODE == 0) { b0 = __ldg(&bias0[cca]); b1v = __ldg(&bias0[cca + 1]); }
                else if (cca < 512) { b0 = __ldg(&bias0[cca]); b1v = __ldg(&bias0[cca + 1]); }
                else { b0 = __ldg(&bias1[cca - 512]); b1v = __ldg(&bias1[cca - 511]); }
                float v0 = acc[mt][nt][half * 2]     + b0;
                float v1 = acc[mt][nt][half * 2 + 1] + b1v;
                if (MODE == 0) {
                    v0 = (v0 > 0.f) ? v0 : 0.1f * v0;
                    v1 = (v1 > 0.f) ? v1 : 0.1f * v1;
                    *(float2*)&g_h[(size_t)row * 1024 + cca] = make_float2(v0, v1);
                } else {
                    if (cca < C_OUT) {
                        *(float2*)&outp[(size_t)row * C_OUT + cca]        = make_float2(v0, v1);
                        *(float2*)&outp[NOUT + (size_t)row * C_OUT + cca] = make_float2(v0, v1);
                    } else {
                        *(float2*)&outp[2 * NOUT + (size_t)row * C_OUT + (cca - C_OUT)]
                            = make_float2(v0, v1);
                    }
                }
            }
        }
    }
}

// ---------------- launcher --------------------------------------------------
extern "C" void kernel_launch(void* const* d_in, const int* in_sizes, int n_in,
                              void* d_out, int out_size) {
    const float* x   = (const float*)d_in[0];
    const void*  ei  = d_in[1];
    const float* W1  = (const float*)d_in[2];
    const float* b1  = (const float*)d_in[3];
    const float* Wm  = (const float*)d_in[4];
    const float* bm  = (const float*)d_in[5];
    const float* Ws  = (const float*)d_in[6];
    const float* bs  = (const float*)d_in[7];
    const float* gw  = (const float*)d_in[8];
    const float* gb  = (const float*)d_in[9];
    const float* gms = (const float*)d_in[10];
    float* out = (float*)d_out;

    dim3 gg(1024 / 128, (N_NODES + 127) / 128);   // (8, 79)

    zero_k   <<<40, 256>>>();
    detect_k <<<(N_EDGES + 255) / 256, 256>>>((const long long*)ei);
    convert_k<<<(2 * N_EDGES + 255) / 256, 256>>>(ei);
    colstats_k<<<dim3(4, 40), 256>>>(x);
    stats_k  <<<4, 256>>>(gw, gb, gms);
    deg_k    <<<(N_EDGES + 255) / 256, 256>>>();
    dis_k    <<<(N_NODES + 255) / 256, 256>>>();
    scan_k   <<<1, 1024>>>();
    scatter_k<<<(N_EDGES + 255) / 256, 256>>>();
    xnorm_k  <<<(N_NODES * 256 + 255) / 256, 256>>>(x);
    convB_k<0><<<dim3(32, 32), dim3(32, 8)>>>(W1, nullptr);
    spmm_pull<0><<<N_NODES, 256>>>();
    gemm_mma<0><<<gg, 256>>>(b1, nullptr, nullptr);
    spmm_pull<1><<<N_NODES, 256>>>();
    convB_k<1><<<dim3(32, 32), dim3(32, 8)>>>(Wm, Ws);
    gemm_mma<1><<<gg, 256>>>(bm, bs, out);
}

// round 8
// speedup vs baseline: 2.1053x; 1.1053x over previous
#include <cuda_runtime.h>
#include <cuda_bf16.h>
#include <cstdint>

#define N_NODES 10000
#define N_EDGES 160000
#define C_IN    1024
#define C_OUT   512
#define KP      3072                       // 3-way split K'
#define NOUT    ((size_t)N_NODES * C_OUT)

// ---------------- scratch (static device globals; no allocations) ----------
// NOTE 1: module-static budget is load-bearing (~170 MB works, 230 MB breaks
// module load). No new large buffers: bf16 A operands reuse dead fp32 buffers.
// NOTE 2: never pass g_* globals as kernel args from host code (host-side
// shadow address + ATS = silent garbage). Reference them in device code only.
__device__ float g_xnorm[(size_t)N_NODES * C_IN];   // fp32 xnorm, then bf16 A for GEMM0
__device__ float g_sx   [(size_t)N_NODES * C_IN];   // S*xnorm,  then bf16 A for GEMM1
__device__ float g_h    [(size_t)N_NODES * 1024];
__device__ float g_sh   [(size_t)N_NODES * 1024];
__device__ float g_colsum [C_IN];
__device__ float g_colsum2[C_IN];
__device__ float g_A[C_IN];
__device__ float g_B[C_IN];
__device__ float g_dis[N_NODES];
__device__ int   g_deg[N_NODES];
__device__ int   g_ei32[2 * N_EDGES];
__device__ int   g_flag32;
// CSR by destination
__device__ int   g_rowptr[N_NODES + 1];
__device__ int   g_cursor[N_NODES];
__device__ int   g_esrc[N_EDGES];
__device__ float g_ew  [N_EDGES];
// bf16 B operand [n][k'] with K-segments [hi, hi, lo]  (6.3 MB)
__device__ __nv_bfloat16 g_bh[(size_t)1024 * KP];

// ---------------- mma helper -------------------------------------------------
__device__ __forceinline__ void mma16816(float* d, const uint32_t* a, const uint32_t* b) {
    asm volatile(
        "mma.sync.aligned.m16n8k16.row.col.f32.bf16.bf16.f32 "
        "{%0,%1,%2,%3}, {%4,%5,%6,%7}, {%8,%9}, {%0,%1,%2,%3};"
        : "+f"(d[0]), "+f"(d[1]), "+f"(d[2]), "+f"(d[3])
        : "r"(a[0]), "r"(a[1]), "r"(a[2]), "r"(a[3]), "r"(b[0]), "r"(b[1]));
}

// ---------------- setup kernels --------------------------------------------
__global__ void zero_k() {
    int i = blockIdx.x * blockDim.x + threadIdx.x;
    if (i < C_IN)    { g_colsum[i] = 0.f; g_colsum2[i] = 0.f; }
    if (i < N_NODES) { g_deg[i] = 0; }
    if (i == 0)      { g_flag32 = 0; }
}

__global__ void detect_k(const long long* __restrict__ ei) {
    int i = blockIdx.x * blockDim.x + threadIdx.x;
    if (i < N_EDGES) {
        long long v = ei[i];
        if (v < 0 || v >= N_NODES) atomicOr(&g_flag32, 1);
    }
}

__global__ void convert_k(const void* __restrict__ ei) {
    int i = blockIdx.x * blockDim.x + threadIdx.x;
    if (i >= 2 * N_EDGES) return;
    g_ei32[i] = g_flag32 ? ((const int*)ei)[i]
                         : (int)((const long long*)ei)[i];
}

__global__ void colstats_k(const float* __restrict__ x) {
    int col = blockIdx.x * 256 + threadIdx.x;
    int r0  = blockIdx.y * 250;
    float s = 0.f, s2 = 0.f;
    for (int r = r0; r < r0 + 250; r++) {
        float v = x[(size_t)r * C_IN + col];
        s += v; s2 += v * v;
    }
    atomicAdd(&g_colsum[col], s);
    atomicAdd(&g_colsum2[col], s2);
}

__global__ void stats_k(const float* __restrict__ w, const float* __restrict__ b,
                        const float* __restrict__ ms) {
    int j = blockIdx.x * blockDim.x + threadIdx.x;
    if (j >= C_IN) return;
    float m   = g_colsum[j]  * (1.f / N_NODES);
    float ex2 = g_colsum2[j] * (1.f / N_NODES);
    float s   = ms[j];
    float var = ex2 - 2.f * s * m * m + s * s * m * m;
    float Aj  = rsqrtf(var + 1e-5f) * w[j];
    g_A[j] = Aj;
    g_B[j] = b[j] - s * m * Aj;
}

__global__ void deg_k() {
    int e = blockIdx.x * blockDim.x + threadIdx.x;
    if (e < N_EDGES) atomicAdd(&g_deg[g_ei32[N_EDGES + e]], 1);
}

__global__ void dis_k() {
    int i = blockIdx.x * blockDim.x + threadIdx.x;
    if (i < N_NODES) g_dis[i] = rsqrtf((float)g_deg[i] + 1.0f);
}

// Single-block exclusive scan of g_deg -> g_rowptr / g_cursor (1024 thr x 10)
__global__ void scan_k() {
    __shared__ int ps[1024];
    int t = threadIdx.x;
    int base = t * 10;
    int loc[10];
    int sum = 0;
    #pragma unroll
    for (int i = 0; i < 10; i++) {
        int idx = base + i;
        int v = (idx < N_NODES) ? g_deg[idx] : 0;
        loc[i] = sum;
        sum += v;
    }
    ps[t] = sum;
    __syncthreads();
    for (int off = 1; off < 1024; off <<= 1) {
        int v = (t >= off) ? ps[t - off] : 0;
        __syncthreads();
        ps[t] += v;
        __syncthreads();
    }
    int excl = ps[t] - sum;
    #pragma unroll
    for (int i = 0; i < 10; i++) {
        int idx = base + i;
        if (idx < N_NODES) {
            int p = excl + loc[i];
            g_rowptr[idx] = p;
            g_cursor[idx] = p;
        }
    }
    if (t == 1023) g_rowptr[N_NODES] = ps[1023];
}

__global__ void scatter_k() {
    int e = blockIdx.x * blockDim.x + threadIdx.x;
    if (e >= N_EDGES) return;
    int s = g_ei32[e];
    int d = g_ei32[N_EDGES + e];
    int pos = atomicAdd(&g_cursor[d], 1);
    g_esrc[pos] = s;
    g_ew[pos]   = g_dis[s] * g_dis[d];
}

__global__ void xnorm_k(const float* __restrict__ x) {
    int i = blockIdx.x * blockDim.x + threadIdx.x;
    if (i >= N_NODES * 256) return;
    int c4 = i & 255;
    float4 xv = ((const float4*)x)[i];
    float4 Av = ((const float4*)g_A)[c4];
    float4 Bv = ((const float4*)g_B)[c4];
    float4 o;
    o.x = fmaf(xv.x, Av.x, Bv.x);
    o.y = fmaf(xv.y, Av.y, Bv.y);
    o.z = fmaf(xv.z, Av.z, Bv.z);
    o.w = fmaf(xv.w, Av.w, Bv.w);
    ((float4*)g_xnorm)[i] = o;
}

// CSR pull SpMM: out[d] = dis[d]^2 * feat[d] + sum_{e: dst=d} w_e * feat[src_e]
template<int PH>
__global__ __launch_bounds__(256) void spmm_pull() {
    const float4* __restrict__ feat = (const float4*)((PH == 0) ? g_xnorm : g_h);
    float4* __restrict__ out        = (float4*)((PH == 0) ? g_sx : g_sh);
    int d = blockIdx.x;
    int t = threadIdx.x;
    int beg = g_rowptr[d], end = g_rowptr[d + 1];
    float dd = g_dis[d]; dd *= dd;
    float4 v0 = feat[(size_t)d * 256 + t];
    float4 acc = make_float4(dd * v0.x, dd * v0.y, dd * v0.z, dd * v0.w);
    int   sn = (beg < end) ? __ldg(&g_esrc[beg]) : 0;
    float wn = (beg < end) ? __ldg(&g_ew[beg])   : 0.f;
    for (int j = beg; j < end; j++) {
        int s = sn; float w = wn;
        if (j + 1 < end) { sn = __ldg(&g_esrc[j + 1]); wn = __ldg(&g_ew[j + 1]); }
        float4 v = feat[(size_t)s * 256 + t];
        acc.x = fmaf(w, v.x, acc.x);
        acc.y = fmaf(w, v.y, acc.y);
        acc.z = fmaf(w, v.z, acc.z);
        acc.w = fmaf(w, v.w, acc.w);
    }
    out[(size_t)d * 256 + t] = acc;
}

// ---------------- A conversion: fp32 [N,1024] -> bf16 [N,2048] = [hi | lo] --
// MODE 0: g_sx -> (bf16)g_xnorm (dead after spmm_pull<0>)
// MODE 1: g_sh -> (bf16)g_sx    (dead after gemm_mma<0>)
// Globals referenced in device code ONLY (see NOTE 2).
template<int MODE>
__global__ void convA_k() {
    const float* __restrict__ src = (MODE == 0) ? g_sx : g_sh;
    __nv_bfloat16* __restrict__ dst =
        (__nv_bfloat16*)((MODE == 0) ? g_xnorm : g_sx);
    int i = blockIdx.x * 256 + threadIdx.x;
    if (i >= N_NODES * 256) return;
    int row = i >> 8;
    int c4  = (i & 255) << 2;
    float4 v = ((const float4*)src)[i];
    __nv_bfloat162 h01 = __floats2bfloat162_rn(v.x, v.y);
    __nv_bfloat162 h23 = __floats2bfloat162_rn(v.z, v.w);
    __nv_bfloat162 l01 = __floats2bfloat162_rn(v.x - __low2float(h01),
                                               v.y - __high2float(h01));
    __nv_bfloat162 l23 = __floats2bfloat162_rn(v.z - __low2float(h23),
                                               v.w - __high2float(h23));
    __nv_bfloat16* base = dst + (size_t)row * 2048;
    uint2 hv, lv;
    hv.x = *(uint32_t*)&h01; hv.y = *(uint32_t*)&h23;
    lv.x = *(uint32_t*)&l01; lv.y = *(uint32_t*)&l23;
    *(uint2*)(base + c4)        = hv;
    *(uint2*)(base + 1024 + c4) = lv;
}

// ---------------- B conversion: fp32 W [k][n] -> g_bh [n][3072] [hi,hi,lo] ---
template<int MODE>
__global__ void convB_k(const float* __restrict__ p0, const float* __restrict__ p1) {
    __shared__ float t[32][33];
    int n0 = blockIdx.x * 32, k0 = blockIdx.y * 32;
    int tx = threadIdx.x, ty = threadIdx.y;         // block (32, 8)
    #pragma unroll
    for (int j = 0; j < 32; j += 8) {
        int k = k0 + ty + j, n = n0 + tx;
        float v;
        if (MODE == 0) v = p0[(size_t)k * 1024 + n];
        else           v = (n < 512) ? p0[(size_t)k * 512 + n]
                                     : p1[(size_t)k * 512 + (n - 512)];
        t[ty + j][tx] = v;
    }
    __syncthreads();
    #pragma unroll
    for (int j = 0; j < 32; j += 8) {
        int n = n0 + ty + j, k = k0 + tx;
        float v = t[tx][ty + j];
        __nv_bfloat16 h = __float2bfloat16(v);
        __nv_bfloat16 l = __float2bfloat16(v - __bfloat162float(h));
        size_t b = (size_t)n * KP + k;
        g_bh[b]        = h;
        g_bh[b + 1024] = h;
        g_bh[b + 2048] = l;
    }
}

// ---------------- mma.sync bf16 GEMM -----------------------------------------
// CTA 128x128, 8 warps (4M x 2N), warp tile 32x64, BK=32 bf16 per chunk.
// A operand pre-split bf16 [row][2048] = [hi | lo]; K' order [hi, lo, hi].
// B pre-split [n][3072] = [hi, hi, lo].
#define ROWB 40
#define NCH  (KP / 32)        // 96 chunks

// byte offset of chunk cn (32 bf16) within a 2048-bf16 [hi|lo] A row
__device__ __forceinline__ int a_koff(int cn) {
    return (((cn >> 5) == 1) ? 2048 : 0) + (cn & 31) * 64;
}

template<int MODE>
__global__ void __launch_bounds__(256) gemm_mma(const float* __restrict__ bias0,
                                                const float* __restrict__ bias1,
                                                float* __restrict__ outp) {
    __shared__ __align__(16) __nv_bfloat16 sA[2][128 * ROWB];
    __shared__ __align__(16) __nv_bfloat16 sB[2][128 * ROWB];

    const __nv_bfloat16* __restrict__ Ap =
        (const __nv_bfloat16*)((MODE == 0) ? g_xnorm : g_sx);
    int tid  = threadIdx.x;
    int lane = tid & 31, w = tid >> 5;
    int wm = w >> 1, wn = w & 1;
    int g = lane >> 2, tig = lane & 3;
    int row0 = blockIdx.y * 128, col0 = blockIdx.x * 128;

    int r0 = tid >> 2;
    int u0b = (tid & 3) * 16;
    int r1 = r0 + 64;
    int ra0 = row0 + r0; if (ra0 >= N_NODES) ra0 = N_NODES - 1;
    int ra1 = row0 + r1; if (ra1 >= N_NODES) ra1 = N_NODES - 1;
    const char* srcA0 = (const char*)(Ap + (size_t)ra0 * 2048) + u0b;
    const char* srcA1 = (const char*)(Ap + (size_t)ra1 * 2048) + u0b;
    const char* srcB0 = (const char*)(g_bh + (size_t)(col0 + r0) * KP) + u0b;
    const char* srcB1 = (const char*)(g_bh + (size_t)(col0 + r1) * KP) + u0b;
    int dst0 = r0 * 80 + u0b;
    int dst1 = r1 * 80 + u0b;

    float acc[2][8][4];
    #pragma unroll
    for (int m = 0; m < 2; m++)
        #pragma unroll
        for (int n = 0; n < 8; n++)
            #pragma unroll
            for (int q = 0; q < 4; q++) acc[m][n][q] = 0.f;

    {
        float4 ua0 = *(const float4*)srcA0;
        float4 ua1 = *(const float4*)srcA1;
        float4 vb0 = *(const float4*)srcB0;
        float4 vb1 = *(const float4*)srcB1;
        *(float4*)((char*)&sA[0][0] + dst0) = ua0;
        *(float4*)((char*)&sA[0][0] + dst1) = ua1;
        *(float4*)((char*)&sB[0][0] + dst0) = vb0;
        *(float4*)((char*)&sB[0][0] + dst1) = vb1;
    }
    __syncthreads();

    int aoff = (wm * 32 + g) * 80 + tig * 4;
    int boff = (wn * 64 + g) * 80 + tig * 4;

    #pragma unroll 1
    for (int c = 0; c < NCH; c++) {
        int b = c & 1;
        bool more = (c + 1 < NCH);
        float4 ua0, ua1, vb0, vb1;
        if (more) {
            int cn = c + 1;
            int ka = a_koff(cn);
            ua0 = *(const float4*)(srcA0 + ka);
            ua1 = *(const float4*)(srcA1 + ka);
            vb0 = *(const float4*)(srcB0 + (size_t)cn * 64);
            vb1 = *(const float4*)(srcB1 + (size_t)cn * 64);
        }
        const char* aB = (const char*)&sA[b][0];
        const char* bB = (const char*)&sB[b][0];
        #pragma unroll
        for (int kt = 0; kt < 2; kt++) {
            uint32_t af[2][4];
            #pragma unroll
            for (int mt = 0; mt < 2; mt++) {
                const char* p = aB + aoff + mt * (16 * 80) + kt * 32;
                af[mt][0] = *(const uint32_t*)(p);
                af[mt][1] = *(const uint32_t*)(p + 640);
                af[mt][2] = *(const uint32_t*)(p + 16);
                af[mt][3] = *(const uint32_t*)(p + 656);
            }
            #pragma unroll
            for (int np = 0; np < 4; np++) {
                const char* p = bB + boff + np * (16 * 80) + kt * 32;
                uint32_t bq[4];
                bq[0] = *(const uint32_t*)(p);
                bq[1] = *(const uint32_t*)(p + 16);
                bq[2] = *(const uint32_t*)(p + 640);
                bq[3] = *(const uint32_t*)(p + 656);
                #pragma unroll
                for (int mt = 0; mt < 2; mt++) {
                    mma16816(acc[mt][np * 2],     af[mt], bq);
                    mma16816(acc[mt][np * 2 + 1], af[mt], bq + 2);
                }
            }
        }
        if (more) {
            int nb = b ^ 1;
            *(float4*)((char*)&sA[nb][0] + dst0) = ua0;
            *(float4*)((char*)&sA[nb][0] + dst1) = ua1;
            *(float4*)((char*)&sB[nb][0] + dst0) = vb0;
            *(float4*)((char*)&sB[nb][0] + dst1) = vb1;
        }
        __syncthreads();
    }

    // ---- epilogue ----
    #pragma unroll
    for (int mt = 0; mt < 2; mt++) {
        int rlo = row0 + wm * 32 + mt * 16 + g;
        #pragma unroll
        for (int half = 0; half < 2; half++) {
            int row = rlo + half * 8;
            if (row >= N_NODES) continue;
            #pragma unroll
            for (int nt = 0; nt < 8; nt++) {
                int cca = col0 + wn * 64 + nt * 8 + tig * 2;
                float b0, b1v;
                if (MODE == 0) { b0 = __ldg(&bias0[cca]); b1v = __ldg(&bias0[cca + 1]); }
                else if (cca < 512) { b0 = __ldg(&bias0[cca]); b1v = __ldg(&bias0[cca + 1]); }
                else { b0 = __ldg(&bias1[cca - 512]); b1v = __ldg(&bias1[cca - 511]); }
                float v0 = acc[mt][nt][half * 2]     + b0;
                float v1 = acc[mt][nt][half * 2 + 1] + b1v;
                if (MODE == 0) {
                    v0 = (v0 > 0.f) ? v0 : 0.1f * v0;
                    v1 = (v1 > 0.f) ? v1 : 0.1f * v1;
                    *(float2*)&g_h[(size_t)row * 1024 + cca] = make_float2(v0, v1);
                } else {
                    if (cca < C_OUT) {
                        *(float2*)&outp[(size_t)row * C_OUT + cca]        = make_float2(v0, v1);
                        *(float2*)&outp[NOUT + (size_t)row * C_OUT + cca] = make_float2(v0, v1);
                    } else {
                        *(float2*)&outp[2 * NOUT + (size_t)row * C_OUT + (cca - C_OUT)]
                            = make_float2(v0, v1);
                    }
                }
            }
        }
    }
}

// ---------------- launcher --------------------------------------------------
extern "C" void kernel_launch(void* const* d_in, const int* in_sizes, int n_in,
                              void* d_out, int out_size) {
    const float* x   = (const float*)d_in[0];
    const void*  ei  = d_in[1];
    const float* W1  = (const float*)d_in[2];
    const float* b1  = (const float*)d_in[3];
    const float* Wm  = (const float*)d_in[4];
    const float* bm  = (const float*)d_in[5];
    const float* Ws  = (const float*)d_in[6];
    const float* bs  = (const float*)d_in[7];
    const float* gw  = (const float*)d_in[8];
    const float* gb  = (const float*)d_in[9];
    const float* gms = (const float*)d_in[10];
    float* out = (float*)d_out;

    dim3 gg(1024 / 128, (N_NODES + 127) / 128);   // (8, 79)
    int convg = (N_NODES * 256 + 255) / 256;

    zero_k   <<<40, 256>>>();
    detect_k <<<(N_EDGES + 255) / 256, 256>>>((const long long*)ei);
    convert_k<<<(2 * N_EDGES + 255) / 256, 256>>>(ei);
    colstats_k<<<dim3(4, 40), 256>>>(x);
    stats_k  <<<4, 256>>>(gw, gb, gms);
    deg_k    <<<(N_EDGES + 255) / 256, 256>>>();
    dis_k    <<<(N_NODES + 255) / 256, 256>>>();
    scan_k   <<<1, 1024>>>();
    scatter_k<<<(N_EDGES + 255) / 256, 256>>>();
    xnorm_k  <<<convg, 256>>>(x);
    convB_k<0><<<dim3(32, 32), dim3(32, 8)>>>(W1, nullptr);
    spmm_pull<0><<<N_NODES, 256>>>();
    convA_k<0><<<convg, 256>>>();      // g_sx -> bf16 A in dead g_xnorm
    gemm_mma<0><<<gg, 256>>>(b1, nullptr, nullptr);
    spmm_pull<1><<<N_NODES, 256>>>();
    convB_k<1><<<dim3(32, 32), dim3(32, 8)>>>(Wm, Ws);
    convA_k<1><<<convg, 256>>>();      // g_sh -> bf16 A in dead g_sx
    gemm_mma<1><<<gg, 256>>>(bm, bs, out);
}

// round 9
// speedup vs baseline: 2.1883x; 1.0394x over previous
#include <cuda_runtime.h>
#include <cuda_bf16.h>
#include <cstdint>

#define N_NODES 10000
#define N_EDGES 160000
#define C_IN    1024
#define C_OUT   512
#define KP      3072                       // 3-way split K'
#define NOUT    ((size_t)N_NODES * C_OUT)

// ---------------- scratch (static device globals; no allocations) ----------
// NOTE 1: module-static budget is load-bearing (~170 MB works, 230 MB breaks
// module load). No new large buffers.
// NOTE 2: never pass g_* globals as kernel args from host code (host-side
// shadow address + ATS = silent garbage). Reference them in device code only.
__device__ float g_xnorm[(size_t)N_NODES * C_IN];   // fp32 normalized x
__device__ float g_sx   [(size_t)N_NODES * C_IN];   // bf16 [hi|lo] A for GEMM0 (written by spmm)
__device__ float g_h    [(size_t)N_NODES * 1024];   // fp32 hidden
__device__ float g_sh   [(size_t)N_NODES * 1024];   // bf16 [hi|lo] A for GEMM1 (written by spmm)
__device__ float g_colsum [C_IN];
__device__ float g_colsum2[C_IN];
__device__ float g_A[C_IN];
__device__ float g_B[C_IN];
__device__ float g_dis[N_NODES];
__device__ int   g_deg[N_NODES];
__device__ int   g_ei32[2 * N_EDGES];
__device__ int   g_flag32;
// CSR by destination
__device__ int   g_rowptr[N_NODES + 1];
__device__ int   g_cursor[N_NODES];
__device__ int   g_esrc[N_EDGES];
__device__ float g_ew  [N_EDGES];
// bf16 B operand [n][k'] with K-segments [hi, hi, lo]  (6.3 MB)
__device__ __nv_bfloat16 g_bh[(size_t)1024 * KP];

// ---------------- asm helpers ------------------------------------------------
__device__ __forceinline__ uint32_t s2u(const void* p) {
    uint32_t a;
    asm("{ .reg .u64 t; cvta.to.shared.u64 t, %1; cvt.u32.u64 %0, t; }"
        : "=r"(a) : "l"(p));
    return a;
}
__device__ __forceinline__ void ldsm4(uint32_t* r, uint32_t addr) {
    asm volatile("ldmatrix.sync.aligned.m8n8.x4.shared.b16 {%0,%1,%2,%3}, [%4];"
                 : "=r"(r[0]), "=r"(r[1]), "=r"(r[2]), "=r"(r[3]) : "r"(addr));
}
__device__ __forceinline__ void mma16816(float* d, const uint32_t* a, const uint32_t* b) {
    asm volatile(
        "mma.sync.aligned.m16n8k16.row.col.f32.bf16.bf16.f32 "
        "{%0,%1,%2,%3}, {%4,%5,%6,%7}, {%8,%9}, {%0,%1,%2,%3};"
        : "+f"(d[0]), "+f"(d[1]), "+f"(d[2]), "+f"(d[3])
        : "r"(a[0]), "r"(a[1]), "r"(a[2]), "r"(a[3]), "r"(b[0]), "r"(b[1]));
}

// ---------------- setup kernels --------------------------------------------
__global__ void zero_k() {
    int i = blockIdx.x * blockDim.x + threadIdx.x;
    if (i < C_IN)    { g_colsum[i] = 0.f; g_colsum2[i] = 0.f; }
    if (i < N_NODES) { g_deg[i] = 0; }
    if (i == 0)      { g_flag32 = 0; }
}

__global__ void detect_k(const long long* __restrict__ ei) {
    int i = blockIdx.x * blockDim.x + threadIdx.x;
    if (i < N_EDGES) {
        long long v = ei[i];
        if (v < 0 || v >= N_NODES) atomicOr(&g_flag32, 1);
    }
}

__global__ void convert_k(const void* __restrict__ ei) {
    int i = blockIdx.x * blockDim.x + threadIdx.x;
    if (i >= 2 * N_EDGES) return;
    g_ei32[i] = g_flag32 ? ((const int*)ei)[i]
                         : (int)((const long long*)ei)[i];
}

__global__ void colstats_k(const float* __restrict__ x) {
    int col = blockIdx.x * 256 + threadIdx.x;
    int r0  = blockIdx.y * 250;
    float s = 0.f, s2 = 0.f;
    for (int r = r0; r < r0 + 250; r++) {
        float v = x[(size_t)r * C_IN + col];
        s += v; s2 += v * v;
    }
    atomicAdd(&g_colsum[col], s);
    atomicAdd(&g_colsum2[col], s2);
}

__global__ void stats_k(const float* __restrict__ w, const float* __restrict__ b,
                        const float* __restrict__ ms) {
    int j = blockIdx.x * blockDim.x + threadIdx.x;
    if (j >= C_IN) return;
    float m   = g_colsum[j]  * (1.f / N_NODES);
    float ex2 = g_colsum2[j] * (1.f / N_NODES);
    float s   = ms[j];
    float var = ex2 - 2.f * s * m * m + s * s * m * m;
    float Aj  = rsqrtf(var + 1e-5f) * w[j];
    g_A[j] = Aj;
    g_B[j] = b[j] - s * m * Aj;
}

__global__ void deg_k() {
    int e = blockIdx.x * blockDim.x + threadIdx.x;
    if (e < N_EDGES) atomicAdd(&g_deg[g_ei32[N_EDGES + e]], 1);
}

__global__ void dis_k() {
    int i = blockIdx.x * blockDim.x + threadIdx.x;
    if (i < N_NODES) g_dis[i] = rsqrtf((float)g_deg[i] + 1.0f);
}

// Single-block exclusive scan of g_deg -> g_rowptr / g_cursor (1024 thr x 10)
__global__ void scan_k() {
    __shared__ int ps[1024];
    int t = threadIdx.x;
    int base = t * 10;
    int loc[10];
    int sum = 0;
    #pragma unroll
    for (int i = 0; i < 10; i++) {
        int idx = base + i;
        int v = (idx < N_NODES) ? g_deg[idx] : 0;
        loc[i] = sum;
        sum += v;
    }
    ps[t] = sum;
    __syncthreads();
    for (int off = 1; off < 1024; off <<= 1) {
        int v = (t >= off) ? ps[t - off] : 0;
        __syncthreads();
        ps[t] += v;
        __syncthreads();
    }
    int excl = ps[t] - sum;
    #pragma unroll
    for (int i = 0; i < 10; i++) {
        int idx = base + i;
        if (idx < N_NODES) {
            int p = excl + loc[i];
            g_rowptr[idx] = p;
            g_cursor[idx] = p;
        }
    }
    if (t == 1023) g_rowptr[N_NODES] = ps[1023];
}

__global__ void scatter_k() {
    int e = blockIdx.x * blockDim.x + threadIdx.x;
    if (e >= N_EDGES) return;
    int s = g_ei32[e];
    int d = g_ei32[N_EDGES + e];
    int pos = atomicAdd(&g_cursor[d], 1);
    g_esrc[pos] = s;
    g_ew[pos]   = g_dis[s] * g_dis[d];
}

__global__ void xnorm_k(const float* __restrict__ x) {
    int i = blockIdx.x * blockDim.x + threadIdx.x;
    if (i >= N_NODES * 256) return;
    int c4 = i & 255;
    float4 xv = ((const float4*)x)[i];
    float4 Av = ((const float4*)g_A)[c4];
    float4 Bv = ((const float4*)g_B)[c4];
    float4 o;
    o.x = fmaf(xv.x, Av.x, Bv.x);
    o.y = fmaf(xv.y, Av.y, Bv.y);
    o.z = fmaf(xv.z, Av.z, Bv.z);
    o.w = fmaf(xv.w, Av.w, Bv.w);
    ((float4*)g_xnorm)[i] = o;
}

// CSR pull SpMM fused with bf16 [hi|lo] split:
//   acc = dis[d]^2*feat[d] + sum w_e*feat[src_e]  (fp32)
//   out row (bf16[2048]): [0:1024)=hi, [1024:2048)=lo
template<int PH>
__global__ __launch_bounds__(256) void spmm_pull() {
    const float4* __restrict__ feat = (const float4*)((PH == 0) ? g_xnorm : g_h);
    __nv_bfloat16* __restrict__ out = (__nv_bfloat16*)((PH == 0) ? g_sx : g_sh);
    int d = blockIdx.x;
    int t = threadIdx.x;
    int beg = g_rowptr[d], end = g_rowptr[d + 1];
    float dd = g_dis[d]; dd *= dd;
    float4 v0 = feat[(size_t)d * 256 + t];
    float4 acc = make_float4(dd * v0.x, dd * v0.y, dd * v0.z, dd * v0.w);
    int   sn = (beg < end) ? __ldg(&g_esrc[beg]) : 0;
    float wn = (beg < end) ? __ldg(&g_ew[beg])   : 0.f;
    for (int j = beg; j < end; j++) {
        int s = sn; float w = wn;
        if (j + 1 < end) { sn = __ldg(&g_esrc[j + 1]); wn = __ldg(&g_ew[j + 1]); }
        float4 v = feat[(size_t)s * 256 + t];
        acc.x = fmaf(w, v.x, acc.x);
        acc.y = fmaf(w, v.y, acc.y);
        acc.z = fmaf(w, v.z, acc.z);
        acc.w = fmaf(w, v.w, acc.w);
    }
    // bf16 hi/lo split, written directly (convA fused away)
    __nv_bfloat162 h01 = __floats2bfloat162_rn(acc.x, acc.y);
    __nv_bfloat162 h23 = __floats2bfloat162_rn(acc.z, acc.w);
    __nv_bfloat162 l01 = __floats2bfloat162_rn(acc.x - __low2float(h01),
                                               acc.y - __high2float(h01));
    __nv_bfloat162 l23 = __floats2bfloat162_rn(acc.z - __low2float(h23),
                                               acc.w - __high2float(h23));
    __nv_bfloat16* base = out + (size_t)d * 2048;
    uint2 hv, lv;
    hv.x = *(uint32_t*)&h01; hv.y = *(uint32_t*)&h23;
    lv.x = *(uint32_t*)&l01; lv.y = *(uint32_t*)&l23;
    *(uint2*)(base + t * 4)        = hv;
    *(uint2*)(base + 1024 + t * 4) = lv;
}

// ---------------- B conversion: fp32 W [k][n] -> g_bh [n][3072] [hi,hi,lo] ---
template<int MODE>
__global__ void convB_k(const float* __restrict__ p0, const float* __restrict__ p1) {
    __shared__ float t[32][33];
    int n0 = blockIdx.x * 32, k0 = blockIdx.y * 32;
    int tx = threadIdx.x, ty = threadIdx.y;         // block (32, 8)
    #pragma unroll
    for (int j = 0; j < 32; j += 8) {
        int k = k0 + ty + j, n = n0 + tx;
        float v;
        if (MODE == 0) v = p0[(size_t)k * 1024 + n];
        else           v = (n < 512) ? p0[(size_t)k * 512 + n]
                                     : p1[(size_t)k * 512 + (n - 512)];
        t[ty + j][tx] = v;
    }
    __syncthreads();
    #pragma unroll
    for (int j = 0; j < 32; j += 8) {
        int n = n0 + ty + j, k = k0 + tx;
        float v = t[tx][ty + j];
        __nv_bfloat16 h = __float2bfloat16(v);
        __nv_bfloat16 l = __float2bfloat16(v - __bfloat162float(h));
        size_t b = (size_t)n * KP + k;
        g_bh[b]        = h;
        g_bh[b + 1024] = h;
        g_bh[b + 2048] = l;
    }
}

// ---------------- mma.sync bf16 GEMM -----------------------------------------
// CTA 128x128, 8 warps (4M x 2N), warp tile 32x64, BK=32 bf16 per chunk.
// A operand pre-split bf16 [row][2048] = [hi | lo]; K' order [hi, lo, hi].
// B pre-split [n][3072] = [hi, hi, lo]. Fragments via ldmatrix.x4
// (mapping verified equivalent to the explicit-LDS layout of R8).
#define ROWB 40
#define NCH  (KP / 32)        // 96 chunks

// byte offset of chunk cn (32 bf16) within a 2048-bf16 [hi|lo] A row
__device__ __forceinline__ int a_koff(int cn) {
    return (((cn >> 5) == 1) ? 2048 : 0) + (cn & 31) * 64;
}

template<int MODE>
__global__ void __launch_bounds__(256) gemm_mma(const float* __restrict__ bias0,
                                                const float* __restrict__ bias1,
                                                float* __restrict__ outp) {
    __shared__ __align__(16) __nv_bfloat16 sA[2][128 * ROWB];
    __shared__ __align__(16) __nv_bfloat16 sB[2][128 * ROWB];

    const __nv_bfloat16* __restrict__ Ap =
        (const __nv_bfloat16*)((MODE == 0) ? g_sx : g_sh);
    int tid  = threadIdx.x;
    int lane = tid & 31, w = tid >> 5;
    int wm = w >> 1, wn = w & 1;
    int g = lane >> 2, tig = lane & 3;
    int row0 = blockIdx.y * 128, col0 = blockIdx.x * 128;

    int r0 = tid >> 2;
    int u0b = (tid & 3) * 16;
    int r1 = r0 + 64;
    int ra0 = row0 + r0; if (ra0 >= N_NODES) ra0 = N_NODES - 1;
    int ra1 = row0 + r1; if (ra1 >= N_NODES) ra1 = N_NODES - 1;
    const char* srcA0 = (const char*)(Ap + (size_t)ra0 * 2048) + u0b;
    const char* srcA1 = (const char*)(Ap + (size_t)ra1 * 2048) + u0b;
    const char* srcB0 = (const char*)(g_bh + (size_t)(col0 + r0) * KP) + u0b;
    const char* srcB1 = (const char*)(g_bh + (size_t)(col0 + r1) * KP) + u0b;
    int dst0 = r0 * 80 + u0b;
    int dst1 = r1 * 80 + u0b;

    // ldmatrix lane addressing (verified layout):
    //   A quad q: rows (q&1)*8 + rin, +16B when q>=2  (reg q = fragment af[q])
    //   B quad q: rows (q>>1)*8 + rin, +16B when q&1  (reg q = fragment bq[q])
    int quad = lane >> 3, rin = lane & 7;
    uint32_t saShared[2] = { s2u(&sA[0][0]), s2u(&sA[1][0]) };
    uint32_t sbShared[2] = { s2u(&sB[0][0]), s2u(&sB[1][0]) };
    uint32_t aLane = (uint32_t)((wm * 32 + (quad & 1) * 8 + rin) * 80 + (quad >> 1) * 16);
    uint32_t bLane = (uint32_t)((wn * 64 + (quad >> 1) * 8 + rin) * 80 + (quad & 1) * 16);

    float acc[2][8][4];
    #pragma unroll
    for (int m = 0; m < 2; m++)
        #pragma unroll
        for (int n = 0; n < 8; n++)
            #pragma unroll
            for (int q = 0; q < 4; q++) acc[m][n][q] = 0.f;

    {
        float4 ua0 = *(const float4*)srcA0;
        float4 ua1 = *(const float4*)srcA1;
        float4 vb0 = *(const float4*)srcB0;
        float4 vb1 = *(const float4*)srcB1;
        *(float4*)((char*)&sA[0][0] + dst0) = ua0;
        *(float4*)((char*)&sA[0][0] + dst1) = ua1;
        *(float4*)((char*)&sB[0][0] + dst0) = vb0;
        *(float4*)((char*)&sB[0][0] + dst1) = vb1;
    }
    __syncthreads();

    #pragma unroll 1
    for (int c = 0; c < NCH; c++) {
        int b = c & 1;
        bool more = (c + 1 < NCH);
        float4 ua0, ua1, vb0, vb1;
        if (more) {
            int cn = c + 1;
            int ka = a_koff(cn);
            ua0 = *(const float4*)(srcA0 + ka);
            ua1 = *(const float4*)(srcA1 + ka);
            vb0 = *(const float4*)(srcB0 + (size_t)cn * 64);
            vb1 = *(const float4*)(srcB1 + (size_t)cn * 64);
        }
        uint32_t aBase = saShared[b] + aLane;
        uint32_t bBase = sbShared[b] + bLane;
        #pragma unroll
        for (int kt = 0; kt < 2; kt++) {
            uint32_t af[2][4];
            ldsm4(af[0], aBase + kt * 32);
            ldsm4(af[1], aBase + 16 * 80 + kt * 32);
            #pragma unroll
            for (int np = 0; np < 4; np++) {
                uint32_t bq[4];
                ldsm4(bq, bBase + np * (16 * 80) + kt * 32);
                #pragma unroll
                for (int mt = 0; mt < 2; mt++) {
                    mma16816(acc[mt][np * 2],     af[mt], bq);
                    mma16816(acc[mt][np * 2 + 1], af[mt], bq + 2);
                }
            }
        }
        if (more) {
            int nb = b ^ 1;
            *(float4*)((char*)&sA[nb][0] + dst0) = ua0;
            *(float4*)((char*)&sA[nb][0] + dst1) = ua1;
            *(float4*)((char*)&sB[nb][0] + dst0) = vb0;
            *(float4*)((char*)&sB[nb][0] + dst1) = vb1;
        }
        __syncthreads();
    }

    // ---- epilogue ----
    #pragma unroll
    for (int mt = 0; mt < 2; mt++) {
        int rlo = row0 + wm * 32 + mt * 16 + g;
        #pragma unroll
        for (int half = 0; half < 2; half++) {
            int row = rlo + half * 8;
            if (row >= N_NODES) continue;
            #pragma unroll
            for (int nt = 0; nt < 8; nt++) {
                int cca = col0 + wn * 64 + nt * 8 + tig * 2;
                float b0, b1v;
                if (MODE == 0) { b0 = __ldg(&bias0[cca]); b1v = __ldg(&bias0[cca + 1]); }
                else if (cca < 512) { b0 = __ldg(&bias0[cca]); b1v = __ldg(&bias0[cca + 1]); }
                else { b0 = __ldg(&bias1[cca - 512]); b1v = __ldg(&bias1[cca - 511]); }
                float v0 = acc[mt][nt][half * 2]     + b0;
                float v1 = acc[mt][nt][half * 2 + 1] + b1v;
                if (MODE == 0) {
                    v0 = (v0 > 0.f) ? v0 : 0.1f * v0;
                    v1 = (v1 > 0.f) ? v1 : 0.1f * v1;
                    *(float2*)&g_h[(size_t)row * 1024 + cca] = make_float2(v0, v1);
                } else {
                    if (cca < C_OUT) {
                        *(float2*)&outp[(size_t)row * C_OUT + cca]        = make_float2(v0, v1);
                        *(float2*)&outp[NOUT + (size_t)row * C_OUT + cca] = make_float2(v0, v1);
                    } else {
                        *(float2*)&outp[2 * NOUT + (size_t)row * C_OUT + (cca - C_OUT)]
                            = make_float2(v0, v1);
                    }
                }
            }
        }
    }
}

// ---------------- launcher --------------------------------------------------
extern "C" void kernel_launch(void* const* d_in, const int* in_sizes, int n_in,
                              void* d_out, int out_size) {
    const float* x   = (const float*)d_in[0];
    const void*  ei  = d_in[1];
    const float* W1  = (const float*)d_in[2];
    const float* b1  = (const float*)d_in[3];
    const float* Wm  = (const float*)d_in[4];
    const float* bm  = (const float*)d_in[5];
    const float* Ws  = (const float*)d_in[6];
    const float* bs  = (const float*)d_in[7];
    const float* gw  = (const float*)d_in[8];
    const float* gb  = (const float*)d_in[9];
    const float* gms = (const float*)d_in[10];
    float* out = (float*)d_out;

    dim3 gg(1024 / 128, (N_NODES + 127) / 128);   // (8, 79)
    int convg = (N_NODES * 256 + 255) / 256;

    zero_k   <<<40, 256>>>();
    detect_k <<<(N_EDGES + 255) / 256, 256>>>((const long long*)ei);
    convert_k<<<(2 * N_EDGES + 255) / 256, 256>>>(ei);
    colstats_k<<<dim3(4, 40), 256>>>(x);
    stats_k  <<<4, 256>>>(gw, gb, gms);
    deg_k    <<<(N_EDGES + 255) / 256, 256>>>();
    dis_k    <<<(N_NODES + 255) / 256, 256>>>();
    scan_k   <<<1, 1024>>>();
    scatter_k<<<(N_EDGES + 255) / 256, 256>>>();
    xnorm_k  <<<convg, 256>>>(x);
    convB_k<0><<<dim3(32, 32), dim3(32, 8)>>>(W1, nullptr);
    spmm_pull<0><<<N_NODES, 256>>>();             // -> bf16 A in g_sx
    gemm_mma<0><<<gg, 256>>>(b1, nullptr, nullptr);
    spmm_pull<1><<<N_NODES, 256>>>();             // -> bf16 A in g_sh
    convB_k<1><<<dim3(32, 32), dim3(32, 8)>>>(Wm, Ws);
    gemm_mma<1><<<gg, 256>>>(bm, bs, out);
}

// round 10
// speedup vs baseline: 2.4698x; 1.1286x over previous
#include <cuda_runtime.h>
#include <cuda_bf16.h>
#include <cstdint>

#define N_NODES 10000
#define N_EDGES 160000
#define C_IN    1024
#define C_OUT   512
#define KP      3072                       // 3-way split K'
#define NOUT    ((size_t)N_NODES * C_OUT)

// ---------------- scratch (static device globals; no allocations) ----------
// NOTE 1: module-static budget is load-bearing (~170 MB works, 230 MB breaks
// module load). No new large buffers.
// NOTE 2: never pass g_* globals as kernel args from host code (host-side
// shadow address + ATS = silent garbage). Reference them in device code only.
__device__ float g_xnorm[(size_t)N_NODES * C_IN];   // fp32 normalized x
__device__ float g_sx   [(size_t)N_NODES * C_IN];   // bf16 [hi|lo] A for GEMM0 (written by spmm)
__device__ float g_h    [(size_t)N_NODES * 1024];   // fp32 hidden
__device__ float g_sh   [(size_t)N_NODES * 1024];   // bf16 [hi|lo] A for GEMM1 (written by spmm)
__device__ float g_colsum [C_IN];
__device__ float g_colsum2[C_IN];
__device__ float g_A[C_IN];
__device__ float g_B[C_IN];
__device__ float g_dis[N_NODES];
__device__ int   g_deg[N_NODES];
__device__ int   g_ei32[2 * N_EDGES];
__device__ int   g_flag32;
// CSR by destination
__device__ int   g_rowptr[N_NODES + 1];
__device__ int   g_cursor[N_NODES];
__device__ int   g_esrc[N_EDGES];
__device__ float g_ew  [N_EDGES];
// bf16 B operand [n][k'] with K-segments [hi, hi, lo]  (6.3 MB)
__device__ __nv_bfloat16 g_bh[(size_t)1024 * KP];

// ---------------- asm helpers ------------------------------------------------
__device__ __forceinline__ uint32_t s2u(const void* p) {
    uint32_t a;
    asm("{ .reg .u64 t; cvta.to.shared.u64 t, %1; cvt.u32.u64 %0, t; }"
        : "=r"(a) : "l"(p));
    return a;
}
__device__ __forceinline__ void ldsm4(uint32_t* r, uint32_t addr) {
    asm volatile("ldmatrix.sync.aligned.m8n8.x4.shared.b16 {%0,%1,%2,%3}, [%4];"
                 : "=r"(r[0]), "=r"(r[1]), "=r"(r[2]), "=r"(r[3]) : "r"(addr));
}
__device__ __forceinline__ void mma16816(float* d, const uint32_t* a, const uint32_t* b) {
    asm volatile(
        "mma.sync.aligned.m16n8k16.row.col.f32.bf16.bf16.f32 "
        "{%0,%1,%2,%3}, {%4,%5,%6,%7}, {%8,%9}, {%0,%1,%2,%3};"
        : "+f"(d[0]), "+f"(d[1]), "+f"(d[2]), "+f"(d[3])
        : "r"(a[0]), "r"(a[1]), "r"(a[2]), "r"(a[3]), "r"(b[0]), "r"(b[1]));
}
#define CPA16(dst, src) \
    asm volatile("cp.async.cg.shared.global [%0], [%1], 16;" \
                 :: "r"(dst), "l"(src))

// ---------------- setup kernels --------------------------------------------
__global__ void zero_k() {
    int i = blockIdx.x * blockDim.x + threadIdx.x;
    if (i < C_IN)    { g_colsum[i] = 0.f; g_colsum2[i] = 0.f; }
    if (i < N_NODES) { g_deg[i] = 0; }
    if (i == 0)      { g_flag32 = 0; }
}

__global__ void detect_k(const long long* __restrict__ ei) {
    int i = blockIdx.x * blockDim.x + threadIdx.x;
    if (i < N_EDGES) {
        long long v = ei[i];
        if (v < 0 || v >= N_NODES) atomicOr(&g_flag32, 1);
    }
}

// convert + fused degree histogram (dst half)
__global__ void convert_k(const void* __restrict__ ei) {
    int i = blockIdx.x * blockDim.x + threadIdx.x;
    if (i >= 2 * N_EDGES) return;
    int v = g_flag32 ? ((const int*)ei)[i]
                     : (int)((const long long*)ei)[i];
    g_ei32[i] = v;
    if (i >= N_EDGES) atomicAdd(&g_deg[v], 1);
}

__global__ void colstats_k(const float* __restrict__ x) {
    int col = blockIdx.x * 256 + threadIdx.x;
    int r0  = blockIdx.y * 250;
    float s = 0.f, s2 = 0.f;
    for (int r = r0; r < r0 + 250; r++) {
        float v = x[(size_t)r * C_IN + col];
        s += v; s2 += v * v;
    }
    atomicAdd(&g_colsum[col], s);
    atomicAdd(&g_colsum2[col], s2);
}

__global__ void stats_k(const float* __restrict__ w, const float* __restrict__ b,
                        const float* __restrict__ ms) {
    int j = blockIdx.x * blockDim.x + threadIdx.x;
    if (j >= C_IN) return;
    float m   = g_colsum[j]  * (1.f / N_NODES);
    float ex2 = g_colsum2[j] * (1.f / N_NODES);
    float s   = ms[j];
    float var = ex2 - 2.f * s * m * m + s * s * m * m;
    float Aj  = rsqrtf(var + 1e-5f) * w[j];
    g_A[j] = Aj;
    g_B[j] = b[j] - s * m * Aj;
}

// Single-block exclusive scan of g_deg -> rowptr/cursor; fused g_dis compute.
__global__ void scan_k() {
    __shared__ int ps[1024];
    int t = threadIdx.x;
    int base = t * 10;
    int loc[10];
    int sum = 0;
    #pragma unroll
    for (int i = 0; i < 10; i++) {
        int idx = base + i;
        int v = (idx < N_NODES) ? g_deg[idx] : 0;
        if (idx < N_NODES) g_dis[idx] = rsqrtf((float)v + 1.0f);
        loc[i] = sum;
        sum += v;
    }
    ps[t] = sum;
    __syncthreads();
    for (int off = 1; off < 1024; off <<= 1) {
        int v = (t >= off) ? ps[t - off] : 0;
        __syncthreads();
        ps[t] += v;
        __syncthreads();
    }
    int excl = ps[t] - sum;
    #pragma unroll
    for (int i = 0; i < 10; i++) {
        int idx = base + i;
        if (idx < N_NODES) {
            int p = excl + loc[i];
            g_rowptr[idx] = p;
            g_cursor[idx] = p;
        }
    }
    if (t == 1023) g_rowptr[N_NODES] = ps[1023];
}

__global__ void scatter_k() {
    int e = blockIdx.x * blockDim.x + threadIdx.x;
    if (e >= N_EDGES) return;
    int s = g_ei32[e];
    int d = g_ei32[N_EDGES + e];
    int pos = atomicAdd(&g_cursor[d], 1);
    g_esrc[pos] = s;
    g_ew[pos]   = g_dis[s] * g_dis[d];
}

__global__ void xnorm_k(const float* __restrict__ x) {
    int i = blockIdx.x * blockDim.x + threadIdx.x;
    if (i >= N_NODES * 256) return;
    int c4 = i & 255;
    float4 xv = ((const float4*)x)[i];
    float4 Av = ((const float4*)g_A)[c4];
    float4 Bv = ((const float4*)g_B)[c4];
    float4 o;
    o.x = fmaf(xv.x, Av.x, Bv.x);
    o.y = fmaf(xv.y, Av.y, Bv.y);
    o.z = fmaf(xv.z, Av.z, Bv.z);
    o.w = fmaf(xv.w, Av.w, Bv.w);
    ((float4*)g_xnorm)[i] = o;
}

// CSR pull SpMM fused with bf16 [hi|lo] split
template<int PH>
__global__ __launch_bounds__(256) void spmm_pull() {
    const float4* __restrict__ feat = (const float4*)((PH == 0) ? g_xnorm : g_h);
    __nv_bfloat16* __restrict__ out = (__nv_bfloat16*)((PH == 0) ? g_sx : g_sh);
    int d = blockIdx.x;
    int t = threadIdx.x;
    int beg = g_rowptr[d], end = g_rowptr[d + 1];
    float dd = g_dis[d]; dd *= dd;
    float4 v0 = feat[(size_t)d * 256 + t];
    float4 acc = make_float4(dd * v0.x, dd * v0.y, dd * v0.z, dd * v0.w);
    int   sn = (beg < end) ? __ldg(&g_esrc[beg]) : 0;
    float wn = (beg < end) ? __ldg(&g_ew[beg])   : 0.f;
    for (int j = beg; j < end; j++) {
        int s = sn; float w = wn;
        if (j + 1 < end) { sn = __ldg(&g_esrc[j + 1]); wn = __ldg(&g_ew[j + 1]); }
        float4 v = feat[(size_t)s * 256 + t];
        acc.x = fmaf(w, v.x, acc.x);
        acc.y = fmaf(w, v.y, acc.y);
        acc.z = fmaf(w, v.z, acc.z);
        acc.w = fmaf(w, v.w, acc.w);
    }
    __nv_bfloat162 h01 = __floats2bfloat162_rn(acc.x, acc.y);
    __nv_bfloat162 h23 = __floats2bfloat162_rn(acc.z, acc.w);
    __nv_bfloat162 l01 = __floats2bfloat162_rn(acc.x - __low2float(h01),
                                               acc.y - __high2float(h01));
    __nv_bfloat162 l23 = __floats2bfloat162_rn(acc.z - __low2float(h23),
                                               acc.w - __high2float(h23));
    __nv_bfloat16* base = out + (size_t)d * 2048;
    uint2 hv, lv;
    hv.x = *(uint32_t*)&h01; hv.y = *(uint32_t*)&h23;
    lv.x = *(uint32_t*)&l01; lv.y = *(uint32_t*)&l23;
    *(uint2*)(base + t * 4)        = hv;
    *(uint2*)(base + 1024 + t * 4) = lv;
}

// ---------------- B conversion: fp32 W [k][n] -> g_bh [n][3072] [hi,hi,lo] ---
template<int MODE>
__global__ void convB_k(const float* __restrict__ p0, const float* __restrict__ p1) {
    __shared__ float t[32][33];
    int n0 = blockIdx.x * 32, k0 = blockIdx.y * 32;
    int tx = threadIdx.x, ty = threadIdx.y;         // block (32, 8)
    #pragma unroll
    for (int j = 0; j < 32; j += 8) {
        int k = k0 + ty + j, n = n0 + tx;
        float v;
        if (MODE == 0) v = p0[(size_t)k * 1024 + n];
        else           v = (n < 512) ? p0[(size_t)k * 512 + n]
                                     : p1[(size_t)k * 512 + (n - 512)];
        t[ty + j][tx] = v;
    }
    __syncthreads();
    #pragma unroll
    for (int j = 0; j < 32; j += 8) {
        int n = n0 + ty + j, k = k0 + tx;
        float v = t[tx][ty + j];
        __nv_bfloat16 h = __float2bfloat16(v);
        __nv_bfloat16 l = __float2bfloat16(v - __bfloat162float(h));
        size_t b = (size_t)n * KP + k;
        g_bh[b]        = h;
        g_bh[b + 1024] = h;
        g_bh[b + 2048] = l;
    }
}

// ---------------- mma.sync bf16 GEMM -----------------------------------------
// CTA 128x128, 8 warps (4M x 2N), warp tile 32x64, BK=32, 4-stage cp.async.
// One __syncthreads per chunk. Safety of lookahead-2 into 4 stages:
// load(c+2) writes stage (c-2)%4; compute(c-2) precedes barrier(c-1), which
// every thread passes before any thread issues load(c+2).
#define ROWB 40
#define NCH  (KP / 32)        // 96 chunks
#define STG_BYTES (128 * 80)  // 10240 per tensor per stage
#define SMEM_DYN (4 * 2 * STG_BYTES)   // 81920

__device__ __forceinline__ int a_koff(int cn) {
    return (((cn >> 5) == 1) ? 2048 : 0) + (cn & 31) * 64;
}

template<int MODE>
__global__ void __launch_bounds__(256) gemm_mma(const float* __restrict__ bias0,
                                                const float* __restrict__ bias1,
                                                float* __restrict__ outp) {
    extern __shared__ char dsm[];
    uint32_t smemA = s2u(dsm);                    // 4 stages x 10240
    uint32_t smemB = smemA + 4 * STG_BYTES;       // 4 stages x 10240

    const __nv_bfloat16* __restrict__ Ap =
        (const __nv_bfloat16*)((MODE == 0) ? g_sx : g_sh);
    int tid  = threadIdx.x;
    int lane = tid & 31, w = tid >> 5;
    int wm = w >> 1, wn = w & 1;
    int g = lane >> 2, tig = lane & 3;
    int row0 = blockIdx.y * 128, col0 = blockIdx.x * 128;

    int r0 = tid >> 2;
    int u0b = (tid & 3) * 16;
    int r1 = r0 + 64;
    int ra0 = row0 + r0; if (ra0 >= N_NODES) ra0 = N_NODES - 1;
    int ra1 = row0 + r1; if (ra1 >= N_NODES) ra1 = N_NODES - 1;
    const char* srcA0 = (const char*)(Ap + (size_t)ra0 * 2048) + u0b;
    const char* srcA1 = (const char*)(Ap + (size_t)ra1 * 2048) + u0b;
    const char* srcB0 = (const char*)(g_bh + (size_t)(col0 + r0) * KP) + u0b;
    const char* srcB1 = (const char*)(g_bh + (size_t)(col0 + r1) * KP) + u0b;
    uint32_t dst0 = (uint32_t)(r0 * 80 + u0b);
    uint32_t dst1 = (uint32_t)(r1 * 80 + u0b);

    int quad = lane >> 3, rin = lane & 7;
    uint32_t aLane = (uint32_t)((wm * 32 + (quad & 1) * 8 + rin) * 80 + (quad >> 1) * 16);
    uint32_t bLane = (uint32_t)((wn * 64 + (quad >> 1) * 8 + rin) * 80 + (quad & 1) * 16);

    float acc[2][8][4];
    #pragma unroll
    for (int m = 0; m < 2; m++)
        #pragma unroll
        for (int n = 0; n < 8; n++)
            #pragma unroll
            for (int q = 0; q < 4; q++) acc[m][n][q] = 0.f;

#define LOADCHUNK(cn, st) do {                                            \
        uint32_t as_ = smemA + (st) * STG_BYTES;                          \
        uint32_t bs_ = smemB + (st) * STG_BYTES;                          \
        int ka_ = a_koff(cn);                                             \
        CPA16(as_ + dst0, srcA0 + ka_);                                   \
        CPA16(as_ + dst1, srcA1 + ka_);                                   \
        CPA16(bs_ + dst0, srcB0 + (size_t)(cn) * 64);                     \
        CPA16(bs_ + dst1, srcB1 + (size_t)(cn) * 64);                     \
        asm volatile("cp.async.commit_group;" ::: "memory");              \
    } while (0)

    // prologue: stages 0,1
    LOADCHUNK(0, 0);
    LOADCHUNK(1, 1);

    #pragma unroll 1
    for (int c = 0; c < NCH; c++) {
        int s = c & 3;
        if (c + 2 < NCH) LOADCHUNK(c + 2, (c + 2) & 3);
        if      (c + 2 < NCH) asm volatile("cp.async.wait_group 2;" ::: "memory");
        else if (c + 1 < NCH) asm volatile("cp.async.wait_group 1;" ::: "memory");
        else                  asm volatile("cp.async.wait_group 0;" ::: "memory");
        __syncthreads();

        uint32_t aBase = smemA + s * STG_BYTES + aLane;
        uint32_t bBase = smemB + s * STG_BYTES + bLane;
        #pragma unroll
        for (int kt = 0; kt < 2; kt++) {
            uint32_t af[2][4];
            ldsm4(af[0], aBase + kt * 32);
            ldsm4(af[1], aBase + 16 * 80 + kt * 32);
            #pragma unroll
            for (int np = 0; np < 4; np++) {
                uint32_t bq[4];
                ldsm4(bq, bBase + np * (16 * 80) + kt * 32);
                #pragma unroll
                for (int mt = 0; mt < 2; mt++) {
                    mma16816(acc[mt][np * 2],     af[mt], bq);
                    mma16816(acc[mt][np * 2 + 1], af[mt], bq + 2);
                }
            }
        }
    }
#undef LOADCHUNK

    // ---- epilogue ----
    #pragma unroll
    for (int mt = 0; mt < 2; mt++) {
        int rlo = row0 + wm * 32 + mt * 16 + g;
        #pragma unroll
        for (int half = 0; half < 2; half++) {
            int row = rlo + half * 8;
            if (row >= N_NODES) continue;
            #pragma unroll
            for (int nt = 0; nt < 8; nt++) {
                int cca = col0 + wn * 64 + nt * 8 + tig * 2;
                float b0, b1v;
                if (MODE == 0) { b0 = __ldg(&bias0[cca]); b1v = __ldg(&bias0[cca + 1]); }
                else if (cca < 512) { b0 = __ldg(&bias0[cca]); b1v = __ldg(&bias0[cca + 1]); }
                else { b0 = __ldg(&bias1[cca - 512]); b1v = __ldg(&bias1[cca - 511]); }
                float v0 = acc[mt][nt][half * 2]     + b0;
                float v1 = acc[mt][nt][half * 2 + 1] + b1v;
                if (MODE == 0) {
                    v0 = (v0 > 0.f) ? v0 : 0.1f * v0;
                    v1 = (v1 > 0.f) ? v1 : 0.1f * v1;
                    *(float2*)&g_h[(size_t)row * 1024 + cca] = make_float2(v0, v1);
                } else {
                    if (cca < C_OUT) {
                        *(float2*)&outp[(size_t)row * C_OUT + cca]        = make_float2(v0, v1);
                        *(float2*)&outp[NOUT + (size_t)row * C_OUT + cca] = make_float2(v0, v1);
                    } else {
                        *(float2*)&outp[2 * NOUT + (size_t)row * C_OUT + (cca - C_OUT)]
                            = make_float2(v0, v1);
                    }
                }
            }
        }
    }
}

// ---------------- launcher --------------------------------------------------
extern "C" void kernel_launch(void* const* d_in, const int* in_sizes, int n_in,
                              void* d_out, int out_size) {
    const float* x   = (const float*)d_in[0];
    const void*  ei  = d_in[1];
    const float* W1  = (const float*)d_in[2];
    const float* b1  = (const float*)d_in[3];
    const float* Wm  = (const float*)d_in[4];
    const float* bm  = (const float*)d_in[5];
    const float* Ws  = (const float*)d_in[6];
    const float* bs  = (const float*)d_in[7];
    const float* gw  = (const float*)d_in[8];
    const float* gb  = (const float*)d_in[9];
    const float* gms = (const float*)d_in[10];
    float* out = (float*)d_out;

    cudaFuncSetAttribute(gemm_mma<0>, cudaFuncAttributeMaxDynamicSharedMemorySize, SMEM_DYN);
    cudaFuncSetAttribute(gemm_mma<1>, cudaFuncAttributeMaxDynamicSharedMemorySize, SMEM_DYN);

    dim3 gg(1024 / 128, (N_NODES + 127) / 128);   // (8, 79)
    int convg = (N_NODES * 256 + 255) / 256;

    zero_k   <<<40, 256>>>();
    detect_k <<<(N_EDGES + 255) / 256, 256>>>((const long long*)ei);
    convert_k<<<(2 * N_EDGES + 255) / 256, 256>>>(ei);   // + fused deg
    colstats_k<<<dim3(4, 40), 256>>>(x);
    stats_k  <<<4, 256>>>(gw, gb, gms);
    scan_k   <<<1, 1024>>>();                            // + fused dis
    scatter_k<<<(N_EDGES + 255) / 256, 256>>>();
    xnorm_k  <<<convg, 256>>>(x);
    convB_k<0><<<dim3(32, 32), dim3(32, 8)>>>(W1, nullptr);
    spmm_pull<0><<<N_NODES, 256>>>();                    // -> bf16 A in g_sx
    gemm_mma<0><<<gg, 256, SMEM_DYN>>>(b1, nullptr, nullptr);
    spmm_pull<1><<<N_NODES, 256>>>();                    // -> bf16 A in g_sh
    convB_k<1><<<dim3(32, 32), dim3(32, 8)>>>(Wm, Ws);
    gemm_mma<1><<<gg, 256, SMEM_DYN>>>(bm, bs, out);
}

// round 11
// speedup vs baseline: 2.5025x; 1.0132x over previous
#include <cuda_runtime.h>
#include <cuda_bf16.h>
#include <cstdint>

#define N_NODES 10000
#define N_EDGES 160000
#define C_IN    1024
#define C_OUT   512
#define KP      3072                       // 3-way split K'
#define NOUT    ((size_t)N_NODES * C_OUT)

// ---------------- scratch (static device globals; no allocations) ----------
// NOTE 1: module-static budget is load-bearing (~170 MB works, 230 MB breaks
// module load). Statics now ~130 MB.
// NOTE 2: never pass g_* globals as kernel args from host code (host-side
// shadow address + ATS = silent garbage). Reference them in device code only.
__device__ float g_sx   [(size_t)N_NODES * C_IN];   // bf16 [hi|lo] A for GEMM0 (written by spmm)
__device__ float g_h    [(size_t)N_NODES * 1024];   // fp32 hidden
__device__ float g_sh   [(size_t)N_NODES * 1024];   // bf16 [hi|lo] A for GEMM1 (written by spmm)
__device__ float g_colsum [C_IN];
__device__ float g_colsum2[C_IN];
__device__ float g_A[C_IN];
__device__ float g_B[C_IN];
__device__ float g_dis[N_NODES];
__device__ int   g_deg[N_NODES];
__device__ int   g_ei32[2 * N_EDGES];
__device__ int   g_flag32;
// CSR by destination
__device__ int   g_rowptr[N_NODES + 1];
__device__ int   g_cursor[N_NODES];
__device__ int   g_esrc[N_EDGES];
__device__ float g_ew  [N_EDGES];
// bf16 B operand [n][k'] with K-segments [hi, hi, lo]  (6.3 MB)
__device__ __nv_bfloat16 g_bh[(size_t)1024 * KP];

// ---------------- asm helpers ------------------------------------------------
__device__ __forceinline__ uint32_t s2u(const void* p) {
    uint32_t a;
    asm("{ .reg .u64 t; cvta.to.shared.u64 t, %1; cvt.u32.u64 %0, t; }"
        : "=r"(a) : "l"(p));
    return a;
}
__device__ __forceinline__ void ldsm4(uint32_t* r, uint32_t addr) {
    asm volatile("ldmatrix.sync.aligned.m8n8.x4.shared.b16 {%0,%1,%2,%3}, [%4];"
                 : "=r"(r[0]), "=r"(r[1]), "=r"(r[2]), "=r"(r[3]) : "r"(addr));
}
__device__ __forceinline__ void mma16816(float* d, const uint32_t* a, const uint32_t* b) {
    asm volatile(
        "mma.sync.aligned.m16n8k16.row.col.f32.bf16.bf16.f32 "
        "{%0,%1,%2,%3}, {%4,%5,%6,%7}, {%8,%9}, {%0,%1,%2,%3};"
        : "+f"(d[0]), "+f"(d[1]), "+f"(d[2]), "+f"(d[3])
        : "r"(a[0]), "r"(a[1]), "r"(a[2]), "r"(a[3]), "r"(b[0]), "r"(b[1]));
}
#define CPA16(dst, src) \
    asm volatile("cp.async.cg.shared.global [%0], [%1], 16;" \
                 :: "r"(dst), "l"(src))

// ---------------- setup kernels --------------------------------------------
__global__ void zero_k() {
    int i = blockIdx.x * blockDim.x + threadIdx.x;
    if (i < C_IN)    { g_colsum[i] = 0.f; g_colsum2[i] = 0.f; }
    if (i < N_NODES) { g_deg[i] = 0; }
    if (i == 0)      { g_flag32 = 0; }
}

__global__ void detect_k(const long long* __restrict__ ei) {
    int i = blockIdx.x * blockDim.x + threadIdx.x;
    if (i < N_EDGES) {
        long long v = ei[i];
        if (v < 0 || v >= N_NODES) atomicOr(&g_flag32, 1);
    }
}

// convert + fused degree histogram (dst half)
__global__ void convert_k(const void* __restrict__ ei) {
    int i = blockIdx.x * blockDim.x + threadIdx.x;
    if (i >= 2 * N_EDGES) return;
    int v = g_flag32 ? ((const int*)ei)[i]
                     : (int)((const long long*)ei)[i];
    g_ei32[i] = v;
    if (i >= N_EDGES) atomicAdd(&g_deg[v], 1);
}

__global__ void colstats_k(const float* __restrict__ x) {
    int col = blockIdx.x * 256 + threadIdx.x;
    int r0  = blockIdx.y * 50;
    float s = 0.f, s2 = 0.f;
    for (int r = r0; r < r0 + 50; r++) {
        float v = x[(size_t)r * C_IN + col];
        s += v; s2 += v * v;
    }
    atomicAdd(&g_colsum[col], s);
    atomicAdd(&g_colsum2[col], s2);
}

__global__ void stats_k(const float* __restrict__ w, const float* __restrict__ b,
                        const float* __restrict__ ms) {
    int j = blockIdx.x * blockDim.x + threadIdx.x;
    if (j >= C_IN) return;
    float m   = g_colsum[j]  * (1.f / N_NODES);
    float ex2 = g_colsum2[j] * (1.f / N_NODES);
    float s   = ms[j];
    float var = ex2 - 2.f * s * m * m + s * s * m * m;
    float Aj  = rsqrtf(var + 1e-5f) * w[j];
    g_A[j] = Aj;
    g_B[j] = b[j] - s * m * Aj;
}

// Single-block exclusive scan of g_deg -> rowptr/cursor; fused g_dis compute.
__global__ void scan_k() {
    __shared__ int ps[1024];
    int t = threadIdx.x;
    int base = t * 10;
    int loc[10];
    int sum = 0;
    #pragma unroll
    for (int i = 0; i < 10; i++) {
        int idx = base + i;
        int v = (idx < N_NODES) ? g_deg[idx] : 0;
        if (idx < N_NODES) g_dis[idx] = rsqrtf((float)v + 1.0f);
        loc[i] = sum;
        sum += v;
    }
    ps[t] = sum;
    __syncthreads();
    for (int off = 1; off < 1024; off <<= 1) {
        int v = (t >= off) ? ps[t - off] : 0;
        __syncthreads();
        ps[t] += v;
        __syncthreads();
    }
    int excl = ps[t] - sum;
    #pragma unroll
    for (int i = 0; i < 10; i++) {
        int idx = base + i;
        if (idx < N_NODES) {
            int p = excl + loc[i];
            g_rowptr[idx] = p;
            g_cursor[idx] = p;
        }
    }
    if (t == 1023) g_rowptr[N_NODES] = ps[1023];
}

__global__ void scatter_k() {
    int e = blockIdx.x * blockDim.x + threadIdx.x;
    if (e >= N_EDGES) return;
    int s = g_ei32[e];
    int d = g_ei32[N_EDGES + e];
    int pos = atomicAdd(&g_cursor[d], 1);
    g_esrc[pos] = s;
    g_ew[pos]   = g_dis[s] * g_dis[d];
}

// CSR pull SpMM fused with bf16 [hi|lo] split.
// PH 0: feat = raw x, GraphNorm fused by linearity:
//       sum w*(A∘x+B) = A∘(sum w*x) + (sum w)*B
// PH 1: feat = g_h (fp32 hidden), no norm.
template<int PH>
__global__ __launch_bounds__(256) void spmm_pull(const float* __restrict__ xin) {
    const float4* __restrict__ feat = (PH == 0) ? (const float4*)xin
                                                : (const float4*)g_h;
    __nv_bfloat16* __restrict__ out = (__nv_bfloat16*)((PH == 0) ? g_sx : g_sh);
    int d = blockIdx.x;
    int t = threadIdx.x;
    int beg = g_rowptr[d], end = g_rowptr[d + 1];
    float dd = g_dis[d]; dd *= dd;
    float4 v0 = feat[(size_t)d * 256 + t];
    float4 acc = make_float4(dd * v0.x, dd * v0.y, dd * v0.z, dd * v0.w);
    float wsum = dd;
    int   sn = (beg < end) ? __ldg(&g_esrc[beg]) : 0;
    float wn = (beg < end) ? __ldg(&g_ew[beg])   : 0.f;
    for (int j = beg; j < end; j++) {
        int s = sn; float w = wn;
        if (j + 1 < end) { sn = __ldg(&g_esrc[j + 1]); wn = __ldg(&g_ew[j + 1]); }
        float4 v = feat[(size_t)s * 256 + t];
        acc.x = fmaf(w, v.x, acc.x);
        acc.y = fmaf(w, v.y, acc.y);
        acc.z = fmaf(w, v.z, acc.z);
        acc.w = fmaf(w, v.w, acc.w);
        wsum += w;
    }
    if (PH == 0) {
        float4 Av = ((const float4*)g_A)[t];
        float4 Bv = ((const float4*)g_B)[t];
        acc.x = fmaf(Av.x, acc.x, wsum * Bv.x);
        acc.y = fmaf(Av.y, acc.y, wsum * Bv.y);
        acc.z = fmaf(Av.z, acc.z, wsum * Bv.z);
        acc.w = fmaf(Av.w, acc.w, wsum * Bv.w);
    }
    __nv_bfloat162 h01 = __floats2bfloat162_rn(acc.x, acc.y);
    __nv_bfloat162 h23 = __floats2bfloat162_rn(acc.z, acc.w);
    __nv_bfloat162 l01 = __floats2bfloat162_rn(acc.x - __low2float(h01),
                                               acc.y - __high2float(h01));
    __nv_bfloat162 l23 = __floats2bfloat162_rn(acc.z - __low2float(h23),
                                               acc.w - __high2float(h23));
    __nv_bfloat16* base = out + (size_t)d * 2048;
    uint2 hv, lv;
    hv.x = *(uint32_t*)&h01; hv.y = *(uint32_t*)&h23;
    lv.x = *(uint32_t*)&l01; lv.y = *(uint32_t*)&l23;
    *(uint2*)(base + t * 4)        = hv;
    *(uint2*)(base + 1024 + t * 4) = lv;
}

// ---------------- B conversion: fp32 W [k][n] -> g_bh [n][3072] [hi,hi,lo] ---
template<int MODE>
__global__ void convB_k(const float* __restrict__ p0, const float* __restrict__ p1) {
    __shared__ float t[32][33];
    int n0 = blockIdx.x * 32, k0 = blockIdx.y * 32;
    int tx = threadIdx.x, ty = threadIdx.y;         // block (32, 8)
    #pragma unroll
    for (int j = 0; j < 32; j += 8) {
        int k = k0 + ty + j, n = n0 + tx;
        float v;
        if (MODE == 0) v = p0[(size_t)k * 1024 + n];
        else           v = (n < 512) ? p0[(size_t)k * 512 + n]
                                     : p1[(size_t)k * 512 + (n - 512)];
        t[ty + j][tx] = v;
    }
    __syncthreads();
    #pragma unroll
    for (int j = 0; j < 32; j += 8) {
        int n = n0 + ty + j, k = k0 + tx;
        float v = t[tx][ty + j];
        __nv_bfloat16 h = __float2bfloat16(v);
        __nv_bfloat16 l = __float2bfloat16(v - __bfloat162float(h));
        size_t b = (size_t)n * KP + k;
        g_bh[b]        = h;
        g_bh[b + 1024] = h;
        g_bh[b + 2048] = l;
    }
}

// ---------------- mma.sync bf16 GEMM -----------------------------------------
// CTA 128x128, 8 warps (4M x 2N), warp tile 32x64, BK=32, 5-stage cp.async,
// lookahead-3, one __syncthreads per chunk.
// Hazards: load(c+3) writes stage (c+3)%5 = (c-2)%5; compute(c-2) precedes
// barrier(c-1), which every thread passed before any thread issues load(c+3).
// Stages {c, c+1, c+2, c+3} distinct mod 5.
#define ROWB 40
#define NCH  (KP / 32)        // 96 chunks
#define STG_BYTES (128 * 80)  // 10240 per tensor per stage
#define SMEM_DYN (5 * 2 * STG_BYTES)   // 102400

__device__ __forceinline__ int a_koff(int cn) {
    return (((cn >> 5) == 1) ? 2048 : 0) + (cn & 31) * 64;
}

template<int MODE>
__global__ void __launch_bounds__(256) gemm_mma(const float* __restrict__ bias0,
                                                const float* __restrict__ bias1,
                                                float* __restrict__ outp) {
    extern __shared__ char dsm[];
    uint32_t smemA = s2u(dsm);                    // 5 stages x 10240
    uint32_t smemB = smemA + 5 * STG_BYTES;       // 5 stages x 10240

    const __nv_bfloat16* __restrict__ Ap =
        (const __nv_bfloat16*)((MODE == 0) ? g_sx : g_sh);
    int tid  = threadIdx.x;
    int lane = tid & 31, w = tid >> 5;
    int wm = w >> 1, wn = w & 1;
    int g = lane >> 2, tig = lane & 3;
    int row0 = blockIdx.y * 128, col0 = blockIdx.x * 128;

    int r0 = tid >> 2;
    int u0b = (tid & 3) * 16;
    int r1 = r0 + 64;
    int ra0 = row0 + r0; if (ra0 >= N_NODES) ra0 = N_NODES - 1;
    int ra1 = row0 + r1; if (ra1 >= N_NODES) ra1 = N_NODES - 1;
    const char* srcA0 = (const char*)(Ap + (size_t)ra0 * 2048) + u0b;
    const char* srcA1 = (const char*)(Ap + (size_t)ra1 * 2048) + u0b;
    const char* srcB0 = (const char*)(g_bh + (size_t)(col0 + r0) * KP) + u0b;
    const char* srcB1 = (const char*)(g_bh + (size_t)(col0 + r1) * KP) + u0b;
    uint32_t dst0 = (uint32_t)(r0 * 80 + u0b);
    uint32_t dst1 = (uint32_t)(r1 * 80 + u0b);

    int quad = lane >> 3, rin = lane & 7;
    uint32_t aLane = (uint32_t)((wm * 32 + (quad & 1) * 8 + rin) * 80 + (quad >> 1) * 16);
    uint32_t bLane = (uint32_t)((wn * 64 + (quad >> 1) * 8 + rin) * 80 + (quad & 1) * 16);

    float acc[2][8][4];
    #pragma unroll
    for (int m = 0; m < 2; m++)
        #pragma unroll
        for (int n = 0; n < 8; n++)
            #pragma unroll
            for (int q = 0; q < 4; q++) acc[m][n][q] = 0.f;

#define LOADCHUNK(cn, st) do {                                            \
        uint32_t as_ = smemA + (st) * STG_BYTES;                          \
        uint32_t bs_ = smemB + (st) * STG_BYTES;                          \
        int ka_ = a_koff(cn);                                             \
        CPA16(as_ + dst0, srcA0 + ka_);                                   \
        CPA16(as_ + dst1, srcA1 + ka_);                                   \
        CPA16(bs_ + dst0, srcB0 + (size_t)(cn) * 64);                     \
        CPA16(bs_ + dst1, srcB1 + (size_t)(cn) * 64);                     \
        asm volatile("cp.async.commit_group;" ::: "memory");              \
    } while (0)

    // prologue: stages 0,1,2
    LOADCHUNK(0, 0);
    LOADCHUNK(1, 1);
    LOADCHUNK(2, 2);

    #pragma unroll 1
    for (int c = 0; c < NCH; c++) {
        int s = c % 5;
        if (c + 3 < NCH) LOADCHUNK(c + 3, (c + 3) % 5);
        if      (c + 3 < NCH) asm volatile("cp.async.wait_group 3;" ::: "memory");
        else if (c + 2 < NCH) asm volatile("cp.async.wait_group 2;" ::: "memory");
        else if (c + 1 < NCH) asm volatile("cp.async.wait_group 1;" ::: "memory");
        else                  asm volatile("cp.async.wait_group 0;" ::: "memory");
        __syncthreads();

        uint32_t aBase = smemA + s * STG_BYTES + aLane;
        uint32_t bBase = smemB + s * STG_BYTES + bLane;
        #pragma unroll
        for (int kt = 0; kt < 2; kt++) {
            uint32_t af[2][4];
            ldsm4(af[0], aBase + kt * 32);
            ldsm4(af[1], aBase + 16 * 80 + kt * 32);
            #pragma unroll
            for (int np = 0; np < 4; np++) {
                uint32_t bq[4];
                ldsm4(bq, bBase + np * (16 * 80) + kt * 32);
                #pragma unroll
                for (int mt = 0; mt < 2; mt++) {
                    mma16816(acc[mt][np * 2],     af[mt], bq);
                    mma16816(acc[mt][np * 2 + 1], af[mt], bq + 2);
                }
            }
        }
    }
#undef LOADCHUNK

    // ---- epilogue ----
    #pragma unroll
    for (int mt = 0; mt < 2; mt++) {
        int rlo = row0 + wm * 32 + mt * 16 + g;
        #pragma unroll
        for (int half = 0; half < 2; half++) {
            int row = rlo + half * 8;
            if (row >= N_NODES) continue;
            #pragma unroll
            for (int nt = 0; nt < 8; nt++) {
                int cca = col0 + wn * 64 + nt * 8 + tig * 2;
                float b0, b1v;
                if (MODE == 0) { b0 = __ldg(&bias0[cca]); b1v = __ldg(&bias0[cca + 1]); }
                else if (cca < 512) { b0 = __ldg(&bias0[cca]); b1v = __ldg(&bias0[cca + 1]); }
                else { b0 = __ldg(&bias1[cca - 512]); b1v = __ldg(&bias1[cca - 511]); }
                float v0 = acc[mt][nt][half * 2]     + b0;
                float v1 = acc[mt][nt][half * 2 + 1] + b1v;
                if (MODE == 0) {
                    v0 = (v0 > 0.f) ? v0 : 0.1f * v0;
                    v1 = (v1 > 0.f) ? v1 : 0.1f * v1;
                    *(float2*)&g_h[(size_t)row * 1024 + cca] = make_float2(v0, v1);
                } else {
                    if (cca < C_OUT) {
                        *(float2*)&outp[(size_t)row * C_OUT + cca]        = make_float2(v0, v1);
                        *(float2*)&outp[NOUT + (size_t)row * C_OUT + cca] = make_float2(v0, v1);
                    } else {
                        *(float2*)&outp[2 * NOUT + (size_t)row * C_OUT + (cca - C_OUT)]
                            = make_float2(v0, v1);
                    }
                }
            }
        }
    }
}

// ---------------- launcher --------------------------------------------------
extern "C" void kernel_launch(void* const* d_in, const int* in_sizes, int n_in,
                              void* d_out, int out_size) {
    const float* x   = (const float*)d_in[0];
    const void*  ei  = d_in[1];
    const float* W1  = (const float*)d_in[2];
    const float* b1  = (const float*)d_in[3];
    const float* Wm  = (const float*)d_in[4];
    const float* bm  = (const float*)d_in[5];
    const float* Ws  = (const float*)d_in[6];
    const float* bs  = (const float*)d_in[7];
    const float* gw  = (const float*)d_in[8];
    const float* gb  = (const float*)d_in[9];
    const float* gms = (const float*)d_in[10];
    float* out = (float*)d_out;

    cudaFuncSetAttribute(gemm_mma<0>, cudaFuncAttributeMaxDynamicSharedMemorySize, SMEM_DYN);
    cudaFuncSetAttribute(gemm_mma<1>, cudaFuncAttributeMaxDynamicSharedMemorySize, SMEM_DYN);

    dim3 gg(1024 / 128, (N_NODES + 127) / 128);   // (8, 79)

    zero_k   <<<40, 256>>>();
    detect_k <<<(N_EDGES + 255) / 256, 256>>>((const long long*)ei);
    convert_k<<<(2 * N_EDGES + 255) / 256, 256>>>(ei);   // + fused deg
    colstats_k<<<dim3(4, 200), 256>>>(x);
    stats_k  <<<4, 256>>>(gw, gb, gms);
    scan_k   <<<1, 1024>>>();                            // + fused dis
    scatter_k<<<(N_EDGES + 255) / 256, 256>>>();
    convB_k<0><<<dim3(32, 32), dim3(32, 8)>>>(W1, nullptr);
    spmm_pull<0><<<N_NODES, 256>>>(x);                   // + fused GraphNorm -> bf16 A in g_sx
    gemm_mma<0><<<gg, 256, SMEM_DYN>>>(b1, nullptr, nullptr);
    spmm_pull<1><<<N_NODES, 256>>>(nullptr);             // -> bf16 A in g_sh
    convB_k<1><<<dim3(32, 32), dim3(32, 8)>>>(Wm, Ws);
    gemm_mma<1><<<gg, 256, SMEM_DYN>>>(bm, bs, out);
}

// round 12
// speedup vs baseline: 2.7409x; 1.0953x over previous
#include <cuda_runtime.h>
#include <cuda_bf16.h>
#include <cstdint>

#define N_NODES 10000
#define N_EDGES 160000
#define C_IN    1024
#define C_OUT   512
#define KP      3072                       // 3-way split K'
#define NOUT    ((size_t)N_NODES * C_OUT)

// ---------------- scratch (static device globals; no allocations) ----------
// NOTE 1: module-static budget is load-bearing (~170 MB works, 230 MB breaks
// module load). Statics ~130 MB.
// NOTE 2: never pass g_* globals as kernel args from host code (host-side
// shadow address + ATS = silent garbage). Reference them in device code only.
__device__ float g_sx   [(size_t)N_NODES * C_IN];   // bf16 [hi|lo] A for GEMM0 (written by spmm)
__device__ float g_h    [(size_t)N_NODES * 1024];   // fp32 hidden
__device__ float g_sh   [(size_t)N_NODES * 1024];   // bf16 [hi|lo] A for GEMM1 (written by spmm)
__device__ float g_colsum [C_IN];
__device__ float g_colsum2[C_IN];
__device__ float g_A[C_IN];
__device__ float g_B[C_IN];
__device__ float g_dis[N_NODES];
__device__ int   g_deg[N_NODES];
__device__ int   g_ei32[2 * N_EDGES];
__device__ int   g_flag32;
// CSR by destination
__device__ int   g_rowptr[N_NODES + 1];
__device__ int   g_cursor[N_NODES];
__device__ int   g_esrc[N_EDGES];
__device__ float g_ew  [N_EDGES];
// bf16 B operand [n][k'] with K-segments [hi, hi, lo]  (6.3 MB)
__device__ __nv_bfloat16 g_bh[(size_t)1024 * KP];

// ---------------- asm helpers ------------------------------------------------
__device__ __forceinline__ uint32_t s2u(const void* p) {
    uint32_t a;
    asm("{ .reg .u64 t; cvta.to.shared.u64 t, %1; cvt.u32.u64 %0, t; }"
        : "=r"(a) : "l"(p));
    return a;
}
__device__ __forceinline__ void ldsm4(uint32_t* r, uint32_t addr) {
    asm volatile("ldmatrix.sync.aligned.m8n8.x4.shared.b16 {%0,%1,%2,%3}, [%4];"
                 : "=r"(r[0]), "=r"(r[1]), "=r"(r[2]), "=r"(r[3]) : "r"(addr));
}
__device__ __forceinline__ void mma16816(float* d, const uint32_t* a, const uint32_t* b) {
    asm volatile(
        "mma.sync.aligned.m16n8k16.row.col.f32.bf16.bf16.f32 "
        "{%0,%1,%2,%3}, {%4,%5,%6,%7}, {%8,%9}, {%0,%1,%2,%3};"
        : "+f"(d[0]), "+f"(d[1]), "+f"(d[2]), "+f"(d[3])
        : "r"(a[0]), "r"(a[1]), "r"(a[2]), "r"(a[3]), "r"(b[0]), "r"(b[1]));
}
#define CPA16(dst, src) \
    asm volatile("cp.async.cg.shared.global [%0], [%1], 16;" \
                 :: "r"(dst), "l"(src))

// ---------------- setup kernels --------------------------------------------
__global__ void zero_k() {
    int i = blockIdx.x * blockDim.x + threadIdx.x;
    if (i < C_IN)    { g_colsum[i] = 0.f; g_colsum2[i] = 0.f; }
    if (i < N_NODES) { g_deg[i] = 0; }
    if (i == 0)      { g_flag32 = 0; }
}

__global__ void detect_k(const long long* __restrict__ ei) {
    int i = blockIdx.x * blockDim.x + threadIdx.x;
    if (i < N_EDGES) {
        long long v = ei[i];
        if (v < 0 || v >= N_NODES) atomicOr(&g_flag32, 1);
    }
}

// convert + fused degree histogram (dst half)
__global__ void convert_k(const void* __restrict__ ei) {
    int i = blockIdx.x * blockDim.x + threadIdx.x;
    if (i >= 2 * N_EDGES) return;
    int v = g_flag32 ? ((const int*)ei)[i]
                     : (int)((const long long*)ei)[i];
    g_ei32[i] = v;
    if (i >= N_EDGES) atomicAdd(&g_deg[v], 1);
}

__global__ void colstats_k(const float* __restrict__ x) {
    int col = blockIdx.x * 256 + threadIdx.x;
    int r0  = blockIdx.y * 25;
    float s = 0.f, s2 = 0.f;
    for (int r = r0; r < r0 + 25; r++) {
        float v = x[(size_t)r * C_IN + col];
        s += v; s2 += v * v;
    }
    atomicAdd(&g_colsum[col], s);
    atomicAdd(&g_colsum2[col], s2);
}

__global__ void stats_k(const float* __restrict__ w, const float* __restrict__ b,
                        const float* __restrict__ ms) {
    int j = blockIdx.x * blockDim.x + threadIdx.x;
    if (j >= C_IN) return;
    float m   = g_colsum[j]  * (1.f / N_NODES);
    float ex2 = g_colsum2[j] * (1.f / N_NODES);
    float s   = ms[j];
    float var = ex2 - 2.f * s * m * m + s * s * m * m;
    float Aj  = rsqrtf(var + 1e-5f) * w[j];
    g_A[j] = Aj;
    g_B[j] = b[j] - s * m * Aj;
}

// Single-block exclusive scan of g_deg -> rowptr/cursor; fused g_dis compute.
__global__ void scan_k() {
    __shared__ int ps[1024];
    int t = threadIdx.x;
    int base = t * 10;
    int loc[10];
    int sum = 0;
    #pragma unroll
    for (int i = 0; i < 10; i++) {
        int idx = base + i;
        int v = (idx < N_NODES) ? g_deg[idx] : 0;
        if (idx < N_NODES) g_dis[idx] = rsqrtf((float)v + 1.0f);
        loc[i] = sum;
        sum += v;
    }
    ps[t] = sum;
    __syncthreads();
    for (int off = 1; off < 1024; off <<= 1) {
        int v = (t >= off) ? ps[t - off] : 0;
        __syncthreads();
        ps[t] += v;
        __syncthreads();
    }
    int excl = ps[t] - sum;
    #pragma unroll
    for (int i = 0; i < 10; i++) {
        int idx = base + i;
        if (idx < N_NODES) {
            int p = excl + loc[i];
            g_rowptr[idx] = p;
            g_cursor[idx] = p;
        }
    }
    if (t == 1023) g_rowptr[N_NODES] = ps[1023];
}

__global__ void scatter_k() {
    int e = blockIdx.x * blockDim.x + threadIdx.x;
    if (e >= N_EDGES) return;
    int s = g_ei32[e];
    int d = g_ei32[N_EDGES + e];
    int pos = atomicAdd(&g_cursor[d], 1);
    g_esrc[pos] = s;
    g_ew[pos]   = g_dis[s] * g_dis[d];
}

// CSR pull SpMM fused with bf16 [hi|lo] split.
// PH 0: feat = raw x, GraphNorm fused by linearity:
//       sum w*(A∘x+B) = A∘(sum w*x) + (sum w)*B
// PH 1: feat = g_h (fp32 hidden), no norm.
template<int PH>
__global__ __launch_bounds__(256) void spmm_pull(const float* __restrict__ xin) {
    const float4* __restrict__ feat = (PH == 0) ? (const float4*)xin
                                                : (const float4*)g_h;
    __nv_bfloat16* __restrict__ out = (__nv_bfloat16*)((PH == 0) ? g_sx : g_sh);
    int d = blockIdx.x;
    int t = threadIdx.x;
    int beg = g_rowptr[d], end = g_rowptr[d + 1];
    float dd = g_dis[d]; dd *= dd;
    float4 v0 = feat[(size_t)d * 256 + t];
    float4 acc = make_float4(dd * v0.x, dd * v0.y, dd * v0.z, dd * v0.w);
    float wsum = dd;
    int   sn = (beg < end) ? __ldg(&g_esrc[beg]) : 0;
    float wn = (beg < end) ? __ldg(&g_ew[beg])   : 0.f;
    for (int j = beg; j < end; j++) {
        int s = sn; float w = wn;
        if (j + 1 < end) { sn = __ldg(&g_esrc[j + 1]); wn = __ldg(&g_ew[j + 1]); }
        float4 v = feat[(size_t)s * 256 + t];
        acc.x = fmaf(w, v.x, acc.x);
        acc.y = fmaf(w, v.y, acc.y);
        acc.z = fmaf(w, v.z, acc.z);
        acc.w = fmaf(w, v.w, acc.w);
        wsum += w;
    }
    if (PH == 0) {
        float4 Av = ((const float4*)g_A)[t];
        float4 Bv = ((const float4*)g_B)[t];
        acc.x = fmaf(Av.x, acc.x, wsum * Bv.x);
        acc.y = fmaf(Av.y, acc.y, wsum * Bv.y);
        acc.z = fmaf(Av.z, acc.z, wsum * Bv.z);
        acc.w = fmaf(Av.w, acc.w, wsum * Bv.w);
    }
    __nv_bfloat162 h01 = __floats2bfloat162_rn(acc.x, acc.y);
    __nv_bfloat162 h23 = __floats2bfloat162_rn(acc.z, acc.w);
    __nv_bfloat162 l01 = __floats2bfloat162_rn(acc.x - __low2float(h01),
                                               acc.y - __high2float(h01));
    __nv_bfloat162 l23 = __floats2bfloat162_rn(acc.z - __low2float(h23),
                                               acc.w - __high2float(h23));
    __nv_bfloat16* base = out + (size_t)d * 2048;
    uint2 hv, lv;
    hv.x = *(uint32_t*)&h01; hv.y = *(uint32_t*)&h23;
    lv.x = *(uint32_t*)&l01; lv.y = *(uint32_t*)&l23;
    *(uint2*)(base + t * 4)        = hv;
    *(uint2*)(base + 1024 + t * 4) = lv;
}

// ---------------- B conversion: fp32 W [k][n] -> g_bh [n][3072] [hi,hi,lo] ---
template<int MODE>
__global__ void convB_k(const float* __restrict__ p0, const float* __restrict__ p1) {
    __shared__ float t[32][33];
    int n0 = blockIdx.x * 32, k0 = blockIdx.y * 32;
    int tx = threadIdx.x, ty = threadIdx.y;         // block (32, 8)
    #pragma unroll
    for (int j = 0; j < 32; j += 8) {
        int k = k0 + ty + j, n = n0 + tx;
        float v;
        if (MODE == 0) v = p0[(size_t)k * 1024 + n];
        else           v = (n < 512) ? p0[(size_t)k * 512 + n]
                                     : p1[(size_t)k * 512 + (n - 512)];
        t[ty + j][tx] = v;
    }
    __syncthreads();
    #pragma unroll
    for (int j = 0; j < 32; j += 8) {
        int n = n0 + ty + j, k = k0 + tx;
        float v = t[tx][ty + j];
        __nv_bfloat16 h = __float2bfloat16(v);
        __nv_bfloat16 l = __float2bfloat16(v - __bfloat162float(h));
        size_t b = (size_t)n * KP + k;
        g_bh[b]        = h;
        g_bh[b + 1024] = h;
        g_bh[b + 2048] = l;
    }
}

// ---------------- mma.sync bf16 GEMM -----------------------------------------
// CTA 128x128, 8 warps (4M x 2N), warp tile 32x64, BK=32, 4-stage cp.async,
// lookahead-2 (R10 config: 80KB smem -> 2 CTAs/SM; R11 showed 5-stage/100KB
// costs ~20us by dropping to 1 CTA/SM).
// Safety: load(c+2) writes stage (c-2)%4; compute(c-2) precedes barrier(c-1),
// which every thread passes before any thread issues load(c+2).
#define ROWB 40
#define NCH  (KP / 32)        // 96 chunks
#define STG_BYTES (128 * 80)  // 10240 per tensor per stage
#define SMEM_DYN (4 * 2 * STG_BYTES)   // 81920

__device__ __forceinline__ int a_koff(int cn) {
    return (((cn >> 5) == 1) ? 2048 : 0) + (cn & 31) * 64;
}

template<int MODE>
__global__ void __launch_bounds__(256, 2) gemm_mma(const float* __restrict__ bias0,
                                                   const float* __restrict__ bias1,
                                                   float* __restrict__ outp) {
    extern __shared__ char dsm[];
    uint32_t smemA = s2u(dsm);                    // 4 stages x 10240
    uint32_t smemB = smemA + 4 * STG_BYTES;       // 4 stages x 10240

    const __nv_bfloat16* __restrict__ Ap =
        (const __nv_bfloat16*)((MODE == 0) ? g_sx : g_sh);
    int tid  = threadIdx.x;
    int lane = tid & 31, w = tid >> 5;
    int wm = w >> 1, wn = w & 1;
    int g = lane >> 2, tig = lane & 3;
    int row0 = blockIdx.y * 128, col0 = blockIdx.x * 128;

    int r0 = tid >> 2;
    int u0b = (tid & 3) * 16;
    int r1 = r0 + 64;
    int ra0 = row0 + r0; if (ra0 >= N_NODES) ra0 = N_NODES - 1;
    int ra1 = row0 + r1; if (ra1 >= N_NODES) ra1 = N_NODES - 1;
    const char* srcA0 = (const char*)(Ap + (size_t)ra0 * 2048) + u0b;
    const char* srcA1 = (const char*)(Ap + (size_t)ra1 * 2048) + u0b;
    const char* srcB0 = (const char*)(g_bh + (size_t)(col0 + r0) * KP) + u0b;
    const char* srcB1 = (const char*)(g_bh + (size_t)(col0 + r1) * KP) + u0b;
    uint32_t dst0 = (uint32_t)(r0 * 80 + u0b);
    uint32_t dst1 = (uint32_t)(r1 * 80 + u0b);

    int quad = lane >> 3, rin = lane & 7;
    uint32_t aLane = (uint32_t)((wm * 32 + (quad & 1) * 8 + rin) * 80 + (quad >> 1) * 16);
    uint32_t bLane = (uint32_t)((wn * 64 + (quad >> 1) * 8 + rin) * 80 + (quad & 1) * 16);

    float acc[2][8][4];
    #pragma unroll
    for (int m = 0; m < 2; m++)
        #pragma unroll
        for (int n = 0; n < 8; n++)
            #pragma unroll
            for (int q = 0; q < 4; q++) acc[m][n][q] = 0.f;

#define LOADCHUNK(cn, st) do {                                            \
        uint32_t as_ = smemA + (st) * STG_BYTES;                          \
        uint32_t bs_ = smemB + (st) * STG_BYTES;                          \
        int ka_ = a_koff(cn);                                             \
        CPA16(as_ + dst0, srcA0 + ka_);                                   \
        CPA16(as_ + dst1, srcA1 + ka_);                                   \
        CPA16(bs_ + dst0, srcB0 + (size_t)(cn) * 64);                     \
        CPA16(bs_ + dst1, srcB1 + (size_t)(cn) * 64);                     \
        asm volatile("cp.async.commit_group;" ::: "memory");              \
    } while (0)

    // prologue: stages 0,1
    LOADCHUNK(0, 0);
    LOADCHUNK(1, 1);

    #pragma unroll 1
    for (int c = 0; c < NCH; c++) {
        int s = c & 3;
        if (c + 2 < NCH) LOADCHUNK(c + 2, (c + 2) & 3);
        if      (c + 2 < NCH) asm volatile("cp.async.wait_group 2;" ::: "memory");
        else if (c + 1 < NCH) asm volatile("cp.async.wait_group 1;" ::: "memory");
        else                  asm volatile("cp.async.wait_group 0;" ::: "memory");
        __syncthreads();

        uint32_t aBase = smemA + s * STG_BYTES + aLane;
        uint32_t bBase = smemB + s * STG_BYTES + bLane;
        #pragma unroll
        for (int kt = 0; kt < 2; kt++) {
            uint32_t af[2][4];
            ldsm4(af[0], aBase + kt * 32);
            ldsm4(af[1], aBase + 16 * 80 + kt * 32);
            #pragma unroll
            for (int np = 0; np < 4; np++) {
                uint32_t bq[4];
                ldsm4(bq, bBase + np * (16 * 80) + kt * 32);
                #pragma unroll
                for (int mt = 0; mt < 2; mt++) {
                    mma16816(acc[mt][np * 2],     af[mt], bq);
                    mma16816(acc[mt][np * 2 + 1], af[mt], bq + 2);
                }
            }
        }
    }
#undef LOADCHUNK

    // ---- epilogue ----
    #pragma unroll
    for (int mt = 0; mt < 2; mt++) {
        int rlo = row0 + wm * 32 + mt * 16 + g;
        #pragma unroll
        for (int half = 0; half < 2; half++) {
            int row = rlo + half * 8;
            if (row >= N_NODES) continue;
            #pragma unroll
            for (int nt = 0; nt < 8; nt++) {
                int cca = col0 + wn * 64 + nt * 8 + tig * 2;
                float b0, b1v;
                if (MODE == 0) { b0 = __ldg(&bias0[cca]); b1v = __ldg(&bias0[cca + 1]); }
                else if (cca < 512) { b0 = __ldg(&bias0[cca]); b1v = __ldg(&bias0[cca + 1]); }
                else { b0 = __ldg(&bias1[cca - 512]); b1v = __ldg(&bias1[cca - 511]); }
                float v0 = acc[mt][nt][half * 2]     + b0;
                float v1 = acc[mt][nt][half * 2 + 1] + b1v;
                if (MODE == 0) {
                    v0 = (v0 > 0.f) ? v0 : 0.1f * v0;
                    v1 = (v1 > 0.f) ? v1 : 0.1f * v1;
                    *(float2*)&g_h[(size_t)row * 1024 + cca] = make_float2(v0, v1);
                } else {
                    if (cca < C_OUT) {
                        *(float2*)&outp[(size_t)row * C_OUT + cca]        = make_float2(v0, v1);
                        *(float2*)&outp[NOUT + (size_t)row * C_OUT + cca] = make_float2(v0, v1);
                    } else {
                        *(float2*)&outp[2 * NOUT + (size_t)row * C_OUT + (cca - C_OUT)]
                            = make_float2(v0, v1);
                    }
                }
            }
        }
    }
}

// ---------------- launcher --------------------------------------------------
extern "C" void kernel_launch(void* const* d_in, const int* in_sizes, int n_in,
                              void* d_out, int out_size) {
    const float* x   = (const float*)d_in[0];
    const void*  ei  = d_in[1];
    const float* W1  = (const float*)d_in[2];
    const float* b1  = (const float*)d_in[3];
    const float* Wm  = (const float*)d_in[4];
    const float* bm  = (const float*)d_in[5];
    const float* Ws  = (const float*)d_in[6];
    const float* bs  = (const float*)d_in[7];
    const float* gw  = (const float*)d_in[8];
    const float* gb  = (const float*)d_in[9];
    const float* gms = (const float*)d_in[10];
    float* out = (float*)d_out;

    cudaFuncSetAttribute(gemm_mma<0>, cudaFuncAttributeMaxDynamicSharedMemorySize, SMEM_DYN);
    cudaFuncSetAttribute(gemm_mma<1>, cudaFuncAttributeMaxDynamicSharedMemorySize, SMEM_DYN);

    dim3 gg(1024 / 128, (N_NODES + 127) / 128);   // (8, 79)

    zero_k   <<<40, 256>>>();
    detect_k <<<(N_EDGES + 255) / 256, 256>>>((const long long*)ei);
    convert_k<<<(2 * N_EDGES + 255) / 256, 256>>>(ei);   // + fused deg
    colstats_k<<<dim3(4, 400), 256>>>(x);
    stats_k  <<<4, 256>>>(gw, gb, gms);
    scan_k   <<<1, 1024>>>();                            // + fused dis
    scatter_k<<<(N_EDGES + 255) / 256, 256>>>();
    convB_k<0><<<dim3(32, 32), dim3(32, 8)>>>(W1, nullptr);
    spmm_pull<0><<<N_NODES, 256>>>(x);                   // + fused GraphNorm -> bf16 A in g_sx
    gemm_mma<0><<<gg, 256, SMEM_DYN>>>(b1, nullptr, nullptr);
    spmm_pull<1><<<N_NODES, 256>>>(nullptr);             // -> bf16 A in g_sh
    convB_k<1><<<dim3(32, 32), dim3(32, 8)>>>(Wm, Ws);
    gemm_mma<1><<<gg, 256, SMEM_DYN>>>(bm, bs, out);
}

// round 13
// speedup vs baseline: 2.7787x; 1.0138x over previous
#include <cuda_runtime.h>
#include <cuda_bf16.h>
#include <cstdint>

#define N_NODES 10000
#define N_EDGES 160000
#define C_IN    1024
#define C_OUT   512
#define KP      3072                       // 3-way split K'
#define NOUT    ((size_t)N_NODES * C_OUT)

// ---------------- scratch (static device globals; no allocations) ----------
// NOTE 1: module-static budget is load-bearing (~170 MB works, 230 MB breaks
// module load). Statics ~137 MB.
// NOTE 2: never pass g_* globals as kernel args from host code (host-side
// shadow address + ATS = silent garbage). Reference them in device code only.
__device__ float g_sx   [(size_t)N_NODES * C_IN];   // bf16 [hi|lo] A for GEMM0 (written by spmm)
__device__ float g_h    [(size_t)N_NODES * 1024];   // fp32 hidden
__device__ float g_sh   [(size_t)N_NODES * 1024];   // bf16 [hi|lo] A for GEMM1 (written by spmm)
__device__ float g_colsum [C_IN];
__device__ float g_colsum2[C_IN];
__device__ float g_A[C_IN];
__device__ float g_B[C_IN];
__device__ float g_dis[N_NODES];
__device__ int   g_deg[N_NODES];
__device__ int   g_ei32[2 * N_EDGES];
__device__ int   g_flag32;
// CSR by destination
__device__ int   g_rowptr[N_NODES + 1];
__device__ int   g_cursor[N_NODES];
__device__ int   g_esrc[N_EDGES];
__device__ float g_ew  [N_EDGES];
// bf16 B operands [n][k'], K-segments [hi, hi, lo]; two buffers so both
// convB's can run concurrently on a side stream (6.3 MB each)
__device__ __nv_bfloat16 g_bh0[(size_t)1024 * KP];
__device__ __nv_bfloat16 g_bh1[(size_t)1024 * KP];

// ---------------- asm helpers ------------------------------------------------
__device__ __forceinline__ uint32_t s2u(const void* p) {
    uint32_t a;
    asm("{ .reg .u64 t; cvta.to.shared.u64 t, %1; cvt.u32.u64 %0, t; }"
        : "=r"(a) : "l"(p));
    return a;
}
__device__ __forceinline__ void ldsm4(uint32_t* r, uint32_t addr) {
    asm volatile("ldmatrix.sync.aligned.m8n8.x4.shared.b16 {%0,%1,%2,%3}, [%4];"
                 : "=r"(r[0]), "=r"(r[1]), "=r"(r[2]), "=r"(r[3]) : "r"(addr));
}
__device__ __forceinline__ void mma16816(float* d, const uint32_t* a, const uint32_t* b) {
    asm volatile(
        "mma.sync.aligned.m16n8k16.row.col.f32.bf16.bf16.f32 "
        "{%0,%1,%2,%3}, {%4,%5,%6,%7}, {%8,%9}, {%0,%1,%2,%3};"
        : "+f"(d[0]), "+f"(d[1]), "+f"(d[2]), "+f"(d[3])
        : "r"(a[0]), "r"(a[1]), "r"(a[2]), "r"(a[3]), "r"(b[0]), "r"(b[1]));
}
#define CPA16(dst, src) \
    asm volatile("cp.async.cg.shared.global [%0], [%1], 16;" \
                 :: "r"(dst), "l"(src))

// ---------------- setup kernels --------------------------------------------
__global__ void zero_k() {
    int i = blockIdx.x * blockDim.x + threadIdx.x;
    if (i < C_IN)    { g_colsum[i] = 0.f; g_colsum2[i] = 0.f; }
    if (i < N_NODES) { g_deg[i] = 0; }
    if (i == 0)      { g_flag32 = 0; }
}

__global__ void detect_k(const long long* __restrict__ ei) {
    int i = blockIdx.x * blockDim.x + threadIdx.x;
    if (i < N_EDGES) {
        long long v = ei[i];
        if (v < 0 || v >= N_NODES) atomicOr(&g_flag32, 1);
    }
}

// convert + fused degree histogram (dst half)
__global__ void convert_k(const void* __restrict__ ei) {
    int i = blockIdx.x * blockDim.x + threadIdx.x;
    if (i >= 2 * N_EDGES) return;
    int v = g_flag32 ? ((const int*)ei)[i]
                     : (int)((const long long*)ei)[i];
    g_ei32[i] = v;
    if (i >= N_EDGES) atomicAdd(&g_deg[v], 1);
}

__global__ void colstats_k(const float* __restrict__ x) {
    int col = blockIdx.x * 256 + threadIdx.x;
    int r0  = blockIdx.y * 25;
    float s = 0.f, s2 = 0.f;
    for (int r = r0; r < r0 + 25; r++) {
        float v = x[(size_t)r * C_IN + col];
        s += v; s2 += v * v;
    }
    atomicAdd(&g_colsum[col], s);
    atomicAdd(&g_colsum2[col], s2);
}

__global__ void stats_k(const float* __restrict__ w, const float* __restrict__ b,
                        const float* __restrict__ ms) {
    int j = blockIdx.x * blockDim.x + threadIdx.x;
    if (j >= C_IN) return;
    float m   = g_colsum[j]  * (1.f / N_NODES);
    float ex2 = g_colsum2[j] * (1.f / N_NODES);
    float s   = ms[j];
    float var = ex2 - 2.f * s * m * m + s * s * m * m;
    float Aj  = rsqrtf(var + 1e-5f) * w[j];
    g_A[j] = Aj;
    g_B[j] = b[j] - s * m * Aj;
}

// Single-block exclusive scan of g_deg -> rowptr/cursor; fused g_dis compute.
__global__ void scan_k() {
    __shared__ int ps[1024];
    int t = threadIdx.x;
    int base = t * 10;
    int loc[10];
    int sum = 0;
    #pragma unroll
    for (int i = 0; i < 10; i++) {
        int idx = base + i;
        int v = (idx < N_NODES) ? g_deg[idx] : 0;
        if (idx < N_NODES) g_dis[idx] = rsqrtf((float)v + 1.0f);
        loc[i] = sum;
        sum += v;
    }
    ps[t] = sum;
    __syncthreads();
    for (int off = 1; off < 1024; off <<= 1) {
        int v = (t >= off) ? ps[t - off] : 0;
        __syncthreads();
        ps[t] += v;
        __syncthreads();
    }
    int excl = ps[t] - sum;
    #pragma unroll
    for (int i = 0; i < 10; i++) {
        int idx = base + i;
        if (idx < N_NODES) {
            int p = excl + loc[i];
            g_rowptr[idx] = p;
            g_cursor[idx] = p;
        }
    }
    if (t == 1023) g_rowptr[N_NODES] = ps[1023];
}

__global__ void scatter_k() {
    int e = blockIdx.x * blockDim.x + threadIdx.x;
    if (e >= N_EDGES) return;
    int s = g_ei32[e];
    int d = g_ei32[N_EDGES + e];
    int pos = atomicAdd(&g_cursor[d], 1);
    g_esrc[pos] = s;
    g_ew[pos]   = g_dis[s] * g_dis[d];
}

// CSR pull SpMM fused with bf16 [hi|lo] split.
// PH 0: feat = raw x, GraphNorm fused by linearity:
//       sum w*(A∘x+B) = A∘(sum w*x) + (sum w)*B
// PH 1: feat = g_h (fp32 hidden), no norm.
template<int PH>
__global__ __launch_bounds__(256) void spmm_pull(const float* __restrict__ xin) {
    const float4* __restrict__ feat = (PH == 0) ? (const float4*)xin
                                                : (const float4*)g_h;
    __nv_bfloat16* __restrict__ out = (__nv_bfloat16*)((PH == 0) ? g_sx : g_sh);
    int d = blockIdx.x;
    int t = threadIdx.x;
    int beg = g_rowptr[d], end = g_rowptr[d + 1];
    float dd = g_dis[d]; dd *= dd;
    float4 v0 = feat[(size_t)d * 256 + t];
    float4 acc = make_float4(dd * v0.x, dd * v0.y, dd * v0.z, dd * v0.w);
    float wsum = dd;
    int   sn = (beg < end) ? __ldg(&g_esrc[beg]) : 0;
    float wn = (beg < end) ? __ldg(&g_ew[beg])   : 0.f;
    for (int j = beg; j < end; j++) {
        int s = sn; float w = wn;
        if (j + 1 < end) { sn = __ldg(&g_esrc[j + 1]); wn = __ldg(&g_ew[j + 1]); }
        float4 v = feat[(size_t)s * 256 + t];
        acc.x = fmaf(w, v.x, acc.x);
        acc.y = fmaf(w, v.y, acc.y);
        acc.z = fmaf(w, v.z, acc.z);
        acc.w = fmaf(w, v.w, acc.w);
        wsum += w;
    }
    if (PH == 0) {
        float4 Av = ((const float4*)g_A)[t];
        float4 Bv = ((const float4*)g_B)[t];
        acc.x = fmaf(Av.x, acc.x, wsum * Bv.x);
        acc.y = fmaf(Av.y, acc.y, wsum * Bv.y);
        acc.z = fmaf(Av.z, acc.z, wsum * Bv.z);
        acc.w = fmaf(Av.w, acc.w, wsum * Bv.w);
    }
    __nv_bfloat162 h01 = __floats2bfloat162_rn(acc.x, acc.y);
    __nv_bfloat162 h23 = __floats2bfloat162_rn(acc.z, acc.w);
    __nv_bfloat162 l01 = __floats2bfloat162_rn(acc.x - __low2float(h01),
                                               acc.y - __high2float(h01));
    __nv_bfloat162 l23 = __floats2bfloat162_rn(acc.z - __low2float(h23),
                                               acc.w - __high2float(h23));
    __nv_bfloat16* base = out + (size_t)d * 2048;
    uint2 hv, lv;
    hv.x = *(uint32_t*)&h01; hv.y = *(uint32_t*)&h23;
    lv.x = *(uint32_t*)&l01; lv.y = *(uint32_t*)&l23;
    *(uint2*)(base + t * 4)        = hv;
    *(uint2*)(base + 1024 + t * 4) = lv;
}

// ---------------- B conversion: fp32 W [k][n] -> g_bhX [n][3072] [hi,hi,lo] --
template<int MODE>
__global__ void convB_k(const float* __restrict__ p0, const float* __restrict__ p1) {
    __nv_bfloat16* __restrict__ gbh = (MODE == 0) ? g_bh0 : g_bh1;
    __shared__ float t[32][33];
    int n0 = blockIdx.x * 32, k0 = blockIdx.y * 32;
    int tx = threadIdx.x, ty = threadIdx.y;         // block (32, 8)
    #pragma unroll
    for (int j = 0; j < 32; j += 8) {
        int k = k0 + ty + j, n = n0 + tx;
        float v;
        if (MODE == 0) v = p0[(size_t)k * 1024 + n];
        else           v = (n < 512) ? p0[(size_t)k * 512 + n]
                                     : p1[(size_t)k * 512 + (n - 512)];
        t[ty + j][tx] = v;
    }
    __syncthreads();
    #pragma unroll
    for (int j = 0; j < 32; j += 8) {
        int n = n0 + ty + j, k = k0 + tx;
        float v = t[tx][ty + j];
        __nv_bfloat16 h = __float2bfloat16(v);
        __nv_bfloat16 l = __float2bfloat16(v - __bfloat162float(h));
        size_t b = (size_t)n * KP + k;
        gbh[b]        = h;
        gbh[b + 1024] = h;
        gbh[b + 2048] = l;
    }
}

// ---------------- mma.sync bf16 GEMM -----------------------------------------
// CTA 128x128, 8 warps (4M x 2N), warp tile 32x64, BK=32, 4-stage cp.async,
// lookahead-2 (80KB smem -> 2 CTAs/SM; R11 showed 5-stage/100KB costs ~20us
// by dropping to 1 CTA/SM).
#define ROWB 40
#define NCH  (KP / 32)        // 96 chunks
#define STG_BYTES (128 * 80)  // 10240 per tensor per stage
#define SMEM_DYN (4 * 2 * STG_BYTES)   // 81920

__device__ __forceinline__ int a_koff(int cn) {
    return (((cn >> 5) == 1) ? 2048 : 0) + (cn & 31) * 64;
}

template<int MODE>
__global__ void __launch_bounds__(256, 2) gemm_mma(const float* __restrict__ bias0,
                                                   const float* __restrict__ bias1,
                                                   float* __restrict__ outp) {
    extern __shared__ char dsm[];
    uint32_t smemA = s2u(dsm);                    // 4 stages x 10240
    uint32_t smemB = smemA + 4 * STG_BYTES;       // 4 stages x 10240

    const __nv_bfloat16* __restrict__ Ap =
        (const __nv_bfloat16*)((MODE == 0) ? g_sx : g_sh);
    const __nv_bfloat16* __restrict__ Bp = (MODE == 0) ? g_bh0 : g_bh1;
    int tid  = threadIdx.x;
    int lane = tid & 31, w = tid >> 5;
    int wm = w >> 1, wn = w & 1;
    int g = lane >> 2, tig = lane & 3;
    int row0 = blockIdx.y * 128, col0 = blockIdx.x * 128;

    int r0 = tid >> 2;
    int u0b = (tid & 3) * 16;
    int r1 = r0 + 64;
    int ra0 = row0 + r0; if (ra0 >= N_NODES) ra0 = N_NODES - 1;
    int ra1 = row0 + r1; if (ra1 >= N_NODES) ra1 = N_NODES - 1;
    const char* srcA0 = (const char*)(Ap + (size_t)ra0 * 2048) + u0b;
    const char* srcA1 = (const char*)(Ap + (size_t)ra1 * 2048) + u0b;
    const char* srcB0 = (const char*)(Bp + (size_t)(col0 + r0) * KP) + u0b;
    const char* srcB1 = (const char*)(Bp + (size_t)(col0 + r1) * KP) + u0b;
    uint32_t dst0 = (uint32_t)(r0 * 80 + u0b);
    uint32_t dst1 = (uint32_t)(r1 * 80 + u0b);

    int quad = lane >> 3, rin = lane & 7;
    uint32_t aLane = (uint32_t)((wm * 32 + (quad & 1) * 8 + rin) * 80 + (quad >> 1) * 16);
    uint32_t bLane = (uint32_t)((wn * 64 + (quad >> 1) * 8 + rin) * 80 + (quad & 1) * 16);

    float acc[2][8][4];
    #pragma unroll
    for (int m = 0; m < 2; m++)
        #pragma unroll
        for (int n = 0; n < 8; n++)
            #pragma unroll
            for (int q = 0; q < 4; q++) acc[m][n][q] = 0.f;

#define LOADCHUNK(cn, st) do {                                            \
        uint32_t as_ = smemA + (st) * STG_BYTES;                          \
        uint32_t bs_ = smemB + (st) * STG_BYTES;                          \
        int ka_ = a_koff(cn);                                             \
        CPA16(as_ + dst0, srcA0 + ka_);                                   \
        CPA16(as_ + dst1, srcA1 + ka_);                                   \
        CPA16(bs_ + dst0, srcB0 + (size_t)(cn) * 64);                     \
        CPA16(bs_ + dst1, srcB1 + (size_t)(cn) * 64);                     \
        asm volatile("cp.async.commit_group;" ::: "memory");              \
    } while (0)

    // prologue: stages 0,1
    LOADCHUNK(0, 0);
    LOADCHUNK(1, 1);

    #pragma unroll 1
    for (int c = 0; c < NCH; c++) {
        int s = c & 3;
        if (c + 2 < NCH) LOADCHUNK(c + 2, (c + 2) & 3);
        if      (c + 2 < NCH) asm volatile("cp.async.wait_group 2;" ::: "memory");
        else if (c + 1 < NCH) asm volatile("cp.async.wait_group 1;" ::: "memory");
        else                  asm volatile("cp.async.wait_group 0;" ::: "memory");
        __syncthreads();

        uint32_t aBase = smemA + s * STG_BYTES + aLane;
        uint32_t bBase = smemB + s * STG_BYTES + bLane;
        #pragma unroll
        for (int kt = 0; kt < 2; kt++) {
            uint32_t af[2][4];
            ldsm4(af[0], aBase + kt * 32);
            ldsm4(af[1], aBase + 16 * 80 + kt * 32);
            #pragma unroll
            for (int np = 0; np < 4; np++) {
                uint32_t bq[4];
                ldsm4(bq, bBase + np * (16 * 80) + kt * 32);
                #pragma unroll
                for (int mt = 0; mt < 2; mt++) {
                    mma16816(acc[mt][np * 2],     af[mt], bq);
                    mma16816(acc[mt][np * 2 + 1], af[mt], bq + 2);
                }
            }
        }
    }
#undef LOADCHUNK

    // ---- epilogue ----
    #pragma unroll
    for (int mt = 0; mt < 2; mt++) {
        int rlo = row0 + wm * 32 + mt * 16 + g;
        #pragma unroll
        for (int half = 0; half < 2; half++) {
            int row = rlo + half * 8;
            if (row >= N_NODES) continue;
            #pragma unroll
            for (int nt = 0; nt < 8; nt++) {
                int cca = col0 + wn * 64 + nt * 8 + tig * 2;
                float b0, b1v;
                if (MODE == 0) { b0 = __ldg(&bias0[cca]); b1v = __ldg(&bias0[cca + 1]); }
                else if (cca < 512) { b0 = __ldg(&bias0[cca]); b1v = __ldg(&bias0[cca + 1]); }
                else { b0 = __ldg(&bias1[cca - 512]); b1v = __ldg(&bias1[cca - 511]); }
                float v0 = acc[mt][nt][half * 2]     + b0;
                float v1 = acc[mt][nt][half * 2 + 1] + b1v;
                if (MODE == 0) {
                    v0 = (v0 > 0.f) ? v0 : 0.1f * v0;
                    v1 = (v1 > 0.f) ? v1 : 0.1f * v1;
                    *(float2*)&g_h[(size_t)row * 1024 + cca] = make_float2(v0, v1);
                } else {
                    if (cca < C_OUT) {
                        *(float2*)&outp[(size_t)row * C_OUT + cca]        = make_float2(v0, v1);
                        *(float2*)&outp[NOUT + (size_t)row * C_OUT + cca] = make_float2(v0, v1);
                    } else {
                        *(float2*)&outp[2 * NOUT + (size_t)row * C_OUT + (cca - C_OUT)]
                            = make_float2(v0, v1);
                    }
                }
            }
        }
    }
}

// ---------------- launcher --------------------------------------------------
// Capture-fork pattern: side streams join via events recorded on the origin
// (capturing) stream. Streams/events are created on the first call — the
// correctness run, which is NOT captured — and reused; the launched work is
// identical on every call.
extern "C" void kernel_launch(void* const* d_in, const int* in_sizes, int n_in,
                              void* d_out, int out_size) {
    const float* x   = (const float*)d_in[0];
    const void*  ei  = d_in[1];
    const float* W1  = (const float*)d_in[2];
    const float* b1  = (const float*)d_in[3];
    const float* Wm  = (const float*)d_in[4];
    const float* bm  = (const float*)d_in[5];
    const float* Ws  = (const float*)d_in[6];
    const float* bs  = (const float*)d_in[7];
    const float* gw  = (const float*)d_in[8];
    const float* gb  = (const float*)d_in[9];
    const float* gms = (const float*)d_in[10];
    float* out = (float*)d_out;

    static cudaStream_t sB = nullptr, sC = nullptr;
    static cudaEvent_t eFork, eStats, eB0, eB1;
    if (sB == nullptr) {
        cudaStreamCreateWithFlags(&sB, cudaStreamNonBlocking);
        cudaStreamCreateWithFlags(&sC, cudaStreamNonBlocking);
        cudaEventCreateWithFlags(&eFork,  cudaEventDisableTiming);
        cudaEventCreateWithFlags(&eStats, cudaEventDisableTiming);
        cudaEventCreateWithFlags(&eB0,    cudaEventDisableTiming);
        cudaEventCreateWithFlags(&eB1,    cudaEventDisableTiming);
        cudaFuncSetAttribute(gemm_mma<0>, cudaFuncAttributeMaxDynamicSharedMemorySize, SMEM_DYN);
        cudaFuncSetAttribute(gemm_mma<1>, cudaFuncAttributeMaxDynamicSharedMemorySize, SMEM_DYN);
    }

    dim3 gg(1024 / 128, (N_NODES + 127) / 128);   // (8, 79)

    // main stream: zeroing (needed by both branches), then fork
    zero_k<<<40, 256>>>();
    cudaEventRecord(eFork, 0);
    cudaStreamWaitEvent(sB, eFork, 0);
    cudaStreamWaitEvent(sC, eFork, 0);

    // branch B: GraphNorm stats (independent of edges)
    colstats_k<<<dim3(4, 400), 256, 0, sB>>>(x);
    stats_k  <<<4, 256, 0, sB>>>(gw, gb, gms);
    cudaEventRecord(eStats, sB);

    // branch C: both weight conversions (independent of everything else)
    convB_k<0><<<dim3(32, 32), dim3(32, 8), 0, sC>>>(W1, nullptr);
    cudaEventRecord(eB0, sC);
    convB_k<1><<<dim3(32, 32), dim3(32, 8), 0, sC>>>(Wm, Ws);
    cudaEventRecord(eB1, sC);

    // main: edge prep chain
    detect_k <<<(N_EDGES + 255) / 256, 256>>>((const long long*)ei);
    convert_k<<<(2 * N_EDGES + 255) / 256, 256>>>(ei);   // + fused deg
    scan_k   <<<1, 1024>>>();                            // + fused dis
    scatter_k<<<(N_EDGES + 255) / 256, 256>>>();

    // join: spmm0 needs stats; gemm0 needs convB0; gemm1 needs convB1
    cudaStreamWaitEvent(0, eStats, 0);
    spmm_pull<0><<<N_NODES, 256>>>(x);                   // + fused GraphNorm -> bf16 A in g_sx
    cudaStreamWaitEvent(0, eB0, 0);
    gemm_mma<0><<<gg, 256, SMEM_DYN>>>(b1, nullptr, nullptr);
    spmm_pull<1><<<N_NODES, 256>>>(nullptr);             // -> bf16 A in g_sh
    cudaStreamWaitEvent(0, eB1, 0);
    gemm_mma<1><<<gg, 256, SMEM_DYN>>>(bm, bs, out);
}